// round 7
// baseline (speedup 1.0000x reference)
#include <cuda_runtime.h>
#include <cstdint>
#include <math.h>

// Problem constants (fixed shapes from reference)
#define BSZ 16384   // batch
#define FF  2048    // n_features
#define HH  4096    // n_hidden
#define DD  4096    // num_of_demos
#define KK  2048    // num_of_features (loss K)

// Scratch (no cudaMalloc allowed)
static __device__ float g_buf0[(size_t)BSZ * HH];
static __device__ float g_buf1[(size_t)BSZ * HH];
static __device__ float g_xr  [(size_t)BSZ * FF];
static __device__ float g_w1r [(size_t)FF  * HH];
static __device__ float g_w2r [(size_t)HH  * HH];
static __device__ float g_w3r [(size_t)HH  * HH];
static __device__ float g_partial[DD];

// ---------------------------------------------------------------------------
// helpers
// ---------------------------------------------------------------------------
__device__ __forceinline__ uint32_t f2tf(float x) {
    uint32_t r;
    asm("cvt.rna.tf32.f32 %0, %1;" : "=r"(r) : "f"(x));
    return r;
}
__device__ __forceinline__ float rna_f(float x) { return __uint_as_float(f2tf(x)); }

__device__ __forceinline__ uint32_t smem_u32(const void* p) {
    uint32_t a;
    asm("{ .reg .u64 t; cvta.to.shared.u64 t, %1; cvt.u32.u64 %0, t; }" : "=r"(a) : "l"(p));
    return a;
}
__device__ __forceinline__ void cp_async16(uint32_t dst, const void* src) {
    asm volatile("cp.async.cg.shared.global [%0], [%1], 16;" :: "r"(dst), "l"(src) : "memory");
}
__device__ __forceinline__ uint32_t lds32(uint32_t addr) {
    uint32_t v;
    asm volatile("ld.shared.b32 %0, [%1];" : "=r"(v) : "r"(addr));
    return v;
}
__device__ __forceinline__ void mma8(float c[4], const uint32_t a[4], const uint32_t b[2]) {
    asm volatile(
        "mma.sync.aligned.m16n8k8.row.col.f32.tf32.tf32.f32 "
        "{%0,%1,%2,%3}, {%4,%5,%6,%7}, {%8,%9}, {%0,%1,%2,%3};\n"
        : "+f"(c[0]), "+f"(c[1]), "+f"(c[2]), "+f"(c[3])
        : "r"(a[0]), "r"(a[1]), "r"(a[2]), "r"(a[3]), "r"(b[0]), "r"(b[1]));
}

__device__ __forceinline__ float block_sum(float v) {
    #pragma unroll
    for (int o = 16; o; o >>= 1) v += __shfl_xor_sync(0xffffffffu, v, o);
    __shared__ float sh[32];
    const int w = threadIdx.x >> 5;
    if ((threadIdx.x & 31) == 0) sh[w] = v;
    __syncthreads();
    const int nw = (blockDim.x + 31) >> 5;
    v = (threadIdx.x < (unsigned)nw) ? sh[threadIdx.x] : 0.f;
    if (threadIdx.x < 32) {
        #pragma unroll
        for (int o = 16; o; o >>= 1) v += __shfl_xor_sync(0xffffffffu, v, o);
    }
    __syncthreads();
    return v;
}

// ---------------------------------------------------------------------------
// prep: elementwise tf32 rounding (x and weights)
// ---------------------------------------------------------------------------
__global__ void round4_kernel(const float* __restrict__ s, float* __restrict__ d, int n4) {
    int i = blockIdx.x * blockDim.x + threadIdx.x;
    if (i < n4) {
        float4 v = ((const float4*)s)[i];
        v.x = rna_f(v.x); v.y = rna_f(v.y); v.z = rna_f(v.z); v.w = rna_f(v.w);
        ((float4*)d)[i] = v;
    }
}

// ---------------------------------------------------------------------------
// Loss kernels (unchanged, passing)
// ---------------------------------------------------------------------------
__global__ void loss_partial_kernel(const float* __restrict__ dm,
                                    const float* __restrict__ alpha,
                                    const float* __restrict__ sl,
                                    const float* __restrict__ cptr) {
    const int j = blockIdx.x;
    const size_t base = (size_t)j * KK;
    const float c = cptr[0];
    float s = 0.f;
    for (int k = threadIdx.x; k < KK; k += blockDim.x) {
        float m = fmaf(alpha[k], sl[base + k] - dm[base + k], 1.0f);
        s += fmaxf(m, 0.f) - c;
    }
    float tot = block_sum(s);
    if (threadIdx.x == 0) g_partial[j] = tot;
}
__global__ void loss_final_kernel(float* __restrict__ lossp) {
    float s = 0.f;
    for (int i = threadIdx.x; i < DD; i += blockDim.x) s += g_partial[i];
    float tot = block_sum(s);
    if (threadIdx.x == 0) lossp[0] = tot;
}

// ---------------------------------------------------------------------------
// GEMM: C[M,N] = rna(relu(A[M,K] @ W[K,N] + bias))
// Block 128x256x32, 256 threads (8 warps as 2Mx4N), warp tile 64x64.
// tf32 mma.sync m16n8k8, fp32 accum. 3-stage cp.async pipeline.
// A smem: 128 rows x 128B, XOR-swizzled 16B chunks (chunk ^= row&7).
// B smem: 32 rows x 1040B (256 floats + 16B pad).
// Inputs must already hold tf32-rounded bits (prep kernels / epilogue).
// ---------------------------------------------------------------------------
#define BM 128
#define BN 256
#define BK 32
#define ASTG 16384            // 128 * 128B
#define BSTG 33280            // 32 * 1040B
#define STG_STRIDE (ASTG + BSTG)
#define SMEM_DYN (3 * STG_STRIDE)

__global__ __launch_bounds__(256, 1)
void gemm_mma(const float* __restrict__ A, const float* __restrict__ W,
              const float* __restrict__ bias, float* __restrict__ C,
              int lda, int N, int ktiles) {
    extern __shared__ char dsm[];
    const uint32_t smb = smem_u32(dsm);

    const int tid = threadIdx.x, lane = tid & 31, wid = tid >> 5;
    const int wm = wid & 1, wn = wid >> 1;      // 2 warps along M, 4 along N
    const int gID = lane >> 2, tig = lane & 3;
    const int bm = blockIdx.y, bn = blockIdx.x;

    const float* Abase = A + (size_t)bm * BM * lda;
    const float* Wbase = W + (size_t)bn * BN;

    // ---- stage fill (cp.async, 12 x 16B per thread) ----
    auto issue_stage = [&](int kt, int s) {
        const float* Ag = Abase + kt * BK;
        const float* Wg = Wbase + (size_t)kt * BK * N;
        const uint32_t sa = smb + s * STG_STRIDE;
        const uint32_t sb = sa + ASTG;
        #pragma unroll
        for (int i = 0; i < 4; ++i) {           // A: 1024 chunks / 256 thr
            const int ci = tid + 256 * i;
            const int r = ci >> 3, cc = ci & 7;
            cp_async16(sa + r * 128 + ((cc ^ (r & 7)) << 4),
                       Ag + (size_t)r * lda + cc * 4);
        }
        #pragma unroll
        for (int i = 0; i < 8; ++i) {           // B: 2048 chunks / 256 thr
            const int ci = tid + 256 * i;
            const int r = ci >> 6, cc = ci & 63;
            cp_async16(sb + r * 1040 + (cc << 4),
                       Wg + (size_t)r * N + cc * 4);
        }
        asm volatile("cp.async.commit_group;" ::: "memory");
    };

    issue_stage(0, 0);
    issue_stage(1, 1);

    float acc[4][8][4];
    #pragma unroll
    for (int mt = 0; mt < 4; ++mt)
        #pragma unroll
        for (int nt = 0; nt < 8; ++nt)
            #pragma unroll
            for (int r = 0; r < 4; ++r) acc[mt][nt][r] = 0.f;

    #pragma unroll 1
    for (int kt = 0; kt < ktiles; ++kt) {
        const int s = kt % 3;
        asm volatile("cp.async.wait_group 1;" ::: "memory");
        __syncthreads();
        if (kt + 2 < ktiles) issue_stage(kt + 2, (kt + 2) % 3);
        else asm volatile("cp.async.commit_group;" ::: "memory");  // keep invariant

        const uint32_t sa = smb + s * STG_STRIDE;
        const uint32_t sb = sa + ASTG;

        #pragma unroll
        for (int kk = 0; kk < BK; kk += 8) {
            const int cch = kk >> 2;
            uint32_t a[4][4], b[8][2];
            #pragma unroll
            for (int mt = 0; mt < 4; ++mt) {
                const int r0 = wm * 64 + mt * 16 + gID;
                const int r1 = r0 + 8;
                const uint32_t b0 = sa + r0 * 128 + (tig << 2);
                const uint32_t b1 = sa + r1 * 128 + (tig << 2);
                a[mt][0] = lds32(b0 + ((cch       ^ (r0 & 7)) << 4));
                a[mt][1] = lds32(b1 + ((cch       ^ (r1 & 7)) << 4));
                a[mt][2] = lds32(b0 + (((cch + 1) ^ (r0 & 7)) << 4));
                a[mt][3] = lds32(b1 + (((cch + 1) ^ (r1 & 7)) << 4));
            }
            #pragma unroll
            for (int nt = 0; nt < 8; ++nt) {
                const int n = wn * 64 + nt * 8 + gID;
                const uint32_t adr = sb + (kk + tig) * 1040 + (n << 2);
                b[nt][0] = lds32(adr);
                b[nt][1] = lds32(adr + 4 * 1040);
            }
            #pragma unroll
            for (int mt = 0; mt < 4; ++mt)
                #pragma unroll
                for (int nt = 0; nt < 8; ++nt)
                    mma8(acc[mt][nt], a[mt], b[nt]);
        }
    }

    // Epilogue: bias + relu + tf32-round, float2 stores
    #pragma unroll
    for (int mt = 0; mt < 4; ++mt) {
        const int m0 = bm * BM + wm * 64 + mt * 16 + gID;
        #pragma unroll
        for (int nt = 0; nt < 8; ++nt) {
            const int n = bn * BN + wn * 64 + nt * 8 + tig * 2;
            const float bx = bias[n], by = bias[n + 1];
            float2 v0, v1;
            v0.x = rna_f(fmaxf(acc[mt][nt][0] + bx, 0.f));
            v0.y = rna_f(fmaxf(acc[mt][nt][1] + by, 0.f));
            v1.x = rna_f(fmaxf(acc[mt][nt][2] + bx, 0.f));
            v1.y = rna_f(fmaxf(acc[mt][nt][3] + by, 0.f));
            *(float2*)&C[(size_t)m0 * N + n]       = v0;
            *(float2*)&C[(size_t)(m0 + 8) * N + n] = v1;
        }
    }
}

// ---------------------------------------------------------------------------
// Final layer: probs = sigmoid(h3 @ W4 + b4) (unchanged, passing)
// ---------------------------------------------------------------------------
__global__ void layer4_kernel(const float* __restrict__ h, const float* __restrict__ w4,
                              const float* __restrict__ b4, float* __restrict__ probs) {
    const int row = blockIdx.x;
    const float* hr = h + (size_t)row * HH;
    float s0 = 0.f, s1 = 0.f;
    for (int k = threadIdx.x; k < HH; k += blockDim.x) {
        const float v = hr[k];
        const float2 w = *(const float2*)(w4 + 2 * k);
        s0 = fmaf(v, w.x, s0);
        s1 = fmaf(v, w.y, s1);
    }
    #pragma unroll
    for (int o = 16; o; o >>= 1) {
        s0 += __shfl_xor_sync(0xffffffffu, s0, o);
        s1 += __shfl_xor_sync(0xffffffffu, s1, o);
    }
    __shared__ float sh0[8], sh1[8];
    const int w = threadIdx.x >> 5;
    if ((threadIdx.x & 31) == 0) { sh0[w] = s0; sh1[w] = s1; }
    __syncthreads();
    if (threadIdx.x == 0) {
        float t0 = 0.f, t1 = 0.f;
        #pragma unroll
        for (int i = 0; i < 8; ++i) { t0 += sh0[i]; t1 += sh1[i]; }
        t0 += b4[0]; t1 += b4[1];
        probs[2 * row]     = 1.f / (1.f + expf(-t0));
        probs[2 * row + 1] = 1.f / (1.f + expf(-t1));
    }
}

// ---------------------------------------------------------------------------
// Launch
// ---------------------------------------------------------------------------
extern "C" void kernel_launch(void* const* d_in, const int* in_sizes, int n_in,
                              void* d_out, int out_size) {
    const int s = (n_in >= 15) ? 0 : -2;
    const float* x     = (const float*)d_in[0];
    const float* dm    = (const float*)d_in[1];
    const float* alpha = (const float*)d_in[2];
    const float* sl    = (const float*)d_in[3];
    const float* cst   = (const float*)d_in[4];
    const float* W1 = (const float*)d_in[7 + s];
    const float* b1 = (const float*)d_in[8 + s];
    const float* W2 = (const float*)d_in[9 + s];
    const float* b2 = (const float*)d_in[10 + s];
    const float* W3 = (const float*)d_in[11 + s];
    const float* b3 = (const float*)d_in[12 + s];
    const float* W4 = (const float*)d_in[13 + s];
    const float* b4 = (const float*)d_in[14 + s];

    float* out = (float*)d_out;
    float* probs = out + (out_size - 2 * BSZ);
    float* lossp = (out_size > 2 * BSZ) ? out : nullptr;

    float *buf0, *buf1, *xr, *w1r, *w2r, *w3r;
    cudaGetSymbolAddress((void**)&buf0, g_buf0);
    cudaGetSymbolAddress((void**)&buf1, g_buf1);
    cudaGetSymbolAddress((void**)&xr,   g_xr);
    cudaGetSymbolAddress((void**)&w1r,  g_w1r);
    cudaGetSymbolAddress((void**)&w2r,  g_w2r);
    cudaGetSymbolAddress((void**)&w3r,  g_w3r);

    // prep: tf32-round x and weights (elementwise; layouts unchanged)
    {
        int n4;
        n4 = BSZ * FF / 4; round4_kernel<<<(n4 + 255) / 256, 256>>>(x,  xr,  n4);
        n4 = FF  * HH / 4; round4_kernel<<<(n4 + 255) / 256, 256>>>(W1, w1r, n4);
        n4 = HH  * HH / 4; round4_kernel<<<(n4 + 255) / 256, 256>>>(W2, w2r, n4);
        n4 = HH  * HH / 4; round4_kernel<<<(n4 + 255) / 256, 256>>>(W3, w3r, n4);
    }

    // loss (deterministic two-pass)
    loss_partial_kernel<<<DD, 256>>>(dm, alpha, sl, cst);
    if (lossp) loss_final_kernel<<<1, 1024>>>(lossp);

    cudaFuncSetAttribute(gemm_mma, cudaFuncAttributeMaxDynamicSharedMemorySize, SMEM_DYN);

    dim3 grid(HH / BN, BSZ / BM);  // (16, 128)
    gemm_mma<<<grid, 256, SMEM_DYN>>>(xr,   w1r, b1, buf0, FF, HH, FF / BK);
    gemm_mma<<<grid, 256, SMEM_DYN>>>(buf0, w2r, b2, buf1, HH, HH, HH / BK);
    gemm_mma<<<grid, 256, SMEM_DYN>>>(buf1, w3r, b3, buf0, HH, HH, HH / BK);

    layer4_kernel<<<BSZ, 256>>>(buf0, W4, b4, probs);
}

// round 8
// speedup vs baseline: 1.0679x; 1.0679x over previous
#include <cuda_runtime.h>
#include <cstdint>
#include <math.h>

// Problem constants (fixed shapes from reference)
#define BSZ 16384   // batch
#define FF  2048    // n_features
#define HH  4096    // n_hidden
#define DD  4096    // num_of_demos
#define KK  2048    // num_of_features (loss K)

// Scratch (no cudaMalloc allowed)
static __device__ float g_buf0[(size_t)BSZ * HH];
static __device__ float g_buf1[(size_t)BSZ * HH];
static __device__ float g_xr  [(size_t)BSZ * FF];
static __device__ float g_w1r [(size_t)FF  * HH];
static __device__ float g_w2r [(size_t)HH  * HH];
static __device__ float g_w3r [(size_t)HH  * HH];
static __device__ float g_partial[DD];

// ---------------------------------------------------------------------------
// helpers
// ---------------------------------------------------------------------------
__device__ __forceinline__ uint32_t f2tf(float x) {
    uint32_t r;
    asm("cvt.rna.tf32.f32 %0, %1;" : "=r"(r) : "f"(x));
    return r;
}
__device__ __forceinline__ float rna_f(float x) { return __uint_as_float(f2tf(x)); }

__device__ __forceinline__ uint32_t smem_u32(const void* p) {
    uint32_t a;
    asm("{ .reg .u64 t; cvta.to.shared.u64 t, %1; cvt.u32.u64 %0, t; }" : "=r"(a) : "l"(p));
    return a;
}
__device__ __forceinline__ void cp_async16(uint32_t dst, const void* src) {
    asm volatile("cp.async.cg.shared.global [%0], [%1], 16;" :: "r"(dst), "l"(src) : "memory");
}
__device__ __forceinline__ uint32_t lds32(uint32_t addr) {
    uint32_t v;
    asm volatile("ld.shared.b32 %0, [%1];" : "=r"(v) : "r"(addr));
    return v;
}
__device__ __forceinline__ void mma8(float c[4], const uint32_t a[4], const uint32_t b[2]) {
    asm volatile(
        "mma.sync.aligned.m16n8k8.row.col.f32.tf32.tf32.f32 "
        "{%0,%1,%2,%3}, {%4,%5,%6,%7}, {%8,%9}, {%0,%1,%2,%3};\n"
        : "+f"(c[0]), "+f"(c[1]), "+f"(c[2]), "+f"(c[3])
        : "r"(a[0]), "r"(a[1]), "r"(a[2]), "r"(a[3]), "r"(b[0]), "r"(b[1]));
}

__device__ __forceinline__ float block_sum(float v) {
    #pragma unroll
    for (int o = 16; o; o >>= 1) v += __shfl_xor_sync(0xffffffffu, v, o);
    __shared__ float sh[32];
    const int w = threadIdx.x >> 5;
    if ((threadIdx.x & 31) == 0) sh[w] = v;
    __syncthreads();
    const int nw = (blockDim.x + 31) >> 5;
    v = (threadIdx.x < (unsigned)nw) ? sh[threadIdx.x] : 0.f;
    if (threadIdx.x < 32) {
        #pragma unroll
        for (int o = 16; o; o >>= 1) v += __shfl_xor_sync(0xffffffffu, v, o);
    }
    __syncthreads();
    return v;
}

// ---------------------------------------------------------------------------
// prep: elementwise tf32 rounding (x and weights)
// ---------------------------------------------------------------------------
__global__ void round4_kernel(const float* __restrict__ s, float* __restrict__ d, int n4) {
    int i = blockIdx.x * blockDim.x + threadIdx.x;
    if (i < n4) {
        float4 v = ((const float4*)s)[i];
        v.x = rna_f(v.x); v.y = rna_f(v.y); v.z = rna_f(v.z); v.w = rna_f(v.w);
        ((float4*)d)[i] = v;
    }
}

// ---------------------------------------------------------------------------
// Loss kernels (unchanged, passing)
// ---------------------------------------------------------------------------
__global__ void loss_partial_kernel(const float* __restrict__ dm,
                                    const float* __restrict__ alpha,
                                    const float* __restrict__ sl,
                                    const float* __restrict__ cptr) {
    const int j = blockIdx.x;
    const size_t base = (size_t)j * KK;
    const float c = cptr[0];
    float s = 0.f;
    for (int k = threadIdx.x; k < KK; k += blockDim.x) {
        float m = fmaf(alpha[k], sl[base + k] - dm[base + k], 1.0f);
        s += fmaxf(m, 0.f) - c;
    }
    float tot = block_sum(s);
    if (threadIdx.x == 0) g_partial[j] = tot;
}
__global__ void loss_final_kernel(float* __restrict__ lossp) {
    float s = 0.f;
    for (int i = threadIdx.x; i < DD; i += blockDim.x) s += g_partial[i];
    float tot = block_sum(s);
    if (threadIdx.x == 0) lossp[0] = tot;
}

// ---------------------------------------------------------------------------
// GEMM: C[M,N] = rna(relu(A[M,K] @ W[K,N] + bias))
// Block 128x256x32, 256 threads (8 warps as 2Mx4N), warp tile 64x64.
// tf32 mma.sync m16n8k8, fp32 accum. 4-stage cp.async pipeline (wait_group 2).
// A smem: 128 rows x 128B, XOR-swizzled 16B chunks (chunk ^= row&7)   [CF]
// B smem: 32 rows x 1056B (264 floats; 264 mod 32 = 8)                 [CF]
//   -> B fragment LDS banks = 8*tig + gID = exact 0..31 permutation.
// Inputs must already hold tf32-rounded bits (prep kernels / epilogue).
// ---------------------------------------------------------------------------
#define BM 128
#define BN 256
#define BK 32
#define BROW 1056             // B smem row stride in bytes (264 floats)
#define ASTG 16384            // 128 * 128B
#define BSTG (32 * BROW)      // 33792
#define STG_STRIDE (ASTG + BSTG)
#define NSTAGE 4
#define SMEM_DYN (NSTAGE * STG_STRIDE)

__global__ __launch_bounds__(256, 1)
void gemm_mma(const float* __restrict__ A, const float* __restrict__ W,
              const float* __restrict__ bias, float* __restrict__ C,
              int lda, int N, int ktiles) {
    extern __shared__ char dsm[];
    const uint32_t smb = smem_u32(dsm);

    const int tid = threadIdx.x, lane = tid & 31, wid = tid >> 5;
    const int wm = wid & 1, wn = wid >> 1;      // 2 warps along M, 4 along N
    const int gID = lane >> 2, tig = lane & 3;
    const int bm = blockIdx.y, bn = blockIdx.x;

    const float* Abase = A + (size_t)bm * BM * lda;
    const float* Wbase = W + (size_t)bn * BN;

    // ---- stage fill (cp.async, 12 x 16B per thread) ----
    auto issue_stage = [&](int kt, int s) {
        const float* Ag = Abase + kt * BK;
        const float* Wg = Wbase + (size_t)kt * BK * N;
        const uint32_t sa = smb + s * STG_STRIDE;
        const uint32_t sb = sa + ASTG;
        #pragma unroll
        for (int i = 0; i < 4; ++i) {           // A: 1024 chunks / 256 thr
            const int ci = tid + 256 * i;
            const int r = ci >> 3, cc = ci & 7;
            cp_async16(sa + r * 128 + ((cc ^ (r & 7)) << 4),
                       Ag + (size_t)r * lda + cc * 4);
        }
        #pragma unroll
        for (int i = 0; i < 8; ++i) {           // B: 2048 chunks / 256 thr
            const int ci = tid + 256 * i;
            const int r = ci >> 6, cc = ci & 63;
            cp_async16(sb + r * BROW + (cc << 4),
                       Wg + (size_t)r * N + cc * 4);
        }
        asm volatile("cp.async.commit_group;" ::: "memory");
    };

    // prologue: fill first 3 stages (keep 2-deep prefetch in steady state)
    issue_stage(0, 0);
    issue_stage(1, 1);
    issue_stage(2, 2);

    float acc[4][8][4];
    #pragma unroll
    for (int mt = 0; mt < 4; ++mt)
        #pragma unroll
        for (int nt = 0; nt < 8; ++nt)
            #pragma unroll
            for (int r = 0; r < 4; ++r) acc[mt][nt][r] = 0.f;

    #pragma unroll 1
    for (int kt = 0; kt < ktiles; ++kt) {
        const int s = kt % NSTAGE;
        asm volatile("cp.async.wait_group 2;" ::: "memory");
        __syncthreads();
        if (kt + 3 < ktiles) issue_stage(kt + 3, (kt + 3) % NSTAGE);
        else asm volatile("cp.async.commit_group;" ::: "memory");  // keep invariant

        const uint32_t sa = smb + s * STG_STRIDE;
        const uint32_t sb = sa + ASTG;

        #pragma unroll
        for (int kk = 0; kk < BK; kk += 8) {
            const int cch = kk >> 2;
            uint32_t a[4][4], b[8][2];
            #pragma unroll
            for (int mt = 0; mt < 4; ++mt) {
                const int r0 = wm * 64 + mt * 16 + gID;
                const int r1 = r0 + 8;
                const uint32_t b0 = sa + r0 * 128 + (tig << 2);
                const uint32_t b1 = sa + r1 * 128 + (tig << 2);
                a[mt][0] = lds32(b0 + ((cch       ^ (r0 & 7)) << 4));
                a[mt][1] = lds32(b1 + ((cch       ^ (r1 & 7)) << 4));
                a[mt][2] = lds32(b0 + (((cch + 1) ^ (r0 & 7)) << 4));
                a[mt][3] = lds32(b1 + (((cch + 1) ^ (r1 & 7)) << 4));
            }
            #pragma unroll
            for (int nt = 0; nt < 8; ++nt) {
                const int n = wn * 64 + nt * 8 + gID;
                const uint32_t adr = sb + (kk + tig) * BROW + (n << 2);
                b[nt][0] = lds32(adr);
                b[nt][1] = lds32(adr + 4 * BROW);
            }
            #pragma unroll
            for (int mt = 0; mt < 4; ++mt)
                #pragma unroll
                for (int nt = 0; nt < 8; ++nt)
                    mma8(acc[mt][nt], a[mt], b[nt]);
        }
    }

    // Epilogue: bias + relu + tf32-round, float2 stores
    #pragma unroll
    for (int mt = 0; mt < 4; ++mt) {
        const int m0 = bm * BM + wm * 64 + mt * 16 + gID;
        #pragma unroll
        for (int nt = 0; nt < 8; ++nt) {
            const int n = bn * BN + wn * 64 + nt * 8 + tig * 2;
            const float bx = bias[n], by = bias[n + 1];
            float2 v0, v1;
            v0.x = rna_f(fmaxf(acc[mt][nt][0] + bx, 0.f));
            v0.y = rna_f(fmaxf(acc[mt][nt][1] + by, 0.f));
            v1.x = rna_f(fmaxf(acc[mt][nt][2] + bx, 0.f));
            v1.y = rna_f(fmaxf(acc[mt][nt][3] + by, 0.f));
            *(float2*)&C[(size_t)m0 * N + n]       = v0;
            *(float2*)&C[(size_t)(m0 + 8) * N + n] = v1;
        }
    }
}

// ---------------------------------------------------------------------------
// Final layer: probs = sigmoid(h3 @ W4 + b4) (unchanged, passing)
// ---------------------------------------------------------------------------
__global__ void layer4_kernel(const float* __restrict__ h, const float* __restrict__ w4,
                              const float* __restrict__ b4, float* __restrict__ probs) {
    const int row = blockIdx.x;
    const float* hr = h + (size_t)row * HH;
    float s0 = 0.f, s1 = 0.f;
    for (int k = threadIdx.x; k < HH; k += blockDim.x) {
        const float v = hr[k];
        const float2 w = *(const float2*)(w4 + 2 * k);
        s0 = fmaf(v, w.x, s0);
        s1 = fmaf(v, w.y, s1);
    }
    #pragma unroll
    for (int o = 16; o; o >>= 1) {
        s0 += __shfl_xor_sync(0xffffffffu, s0, o);
        s1 += __shfl_xor_sync(0xffffffffu, s1, o);
    }
    __shared__ float sh0[8], sh1[8];
    const int w = threadIdx.x >> 5;
    if ((threadIdx.x & 31) == 0) { sh0[w] = s0; sh1[w] = s1; }
    __syncthreads();
    if (threadIdx.x == 0) {
        float t0 = 0.f, t1 = 0.f;
        #pragma unroll
        for (int i = 0; i < 8; ++i) { t0 += sh0[i]; t1 += sh1[i]; }
        t0 += b4[0]; t1 += b4[1];
        probs[2 * row]     = 1.f / (1.f + expf(-t0));
        probs[2 * row + 1] = 1.f / (1.f + expf(-t1));
    }
}

// ---------------------------------------------------------------------------
// Launch
// ---------------------------------------------------------------------------
extern "C" void kernel_launch(void* const* d_in, const int* in_sizes, int n_in,
                              void* d_out, int out_size) {
    const int s = (n_in >= 15) ? 0 : -2;
    const float* x     = (const float*)d_in[0];
    const float* dm    = (const float*)d_in[1];
    const float* alpha = (const float*)d_in[2];
    const float* sl    = (const float*)d_in[3];
    const float* cst   = (const float*)d_in[4];
    const float* W1 = (const float*)d_in[7 + s];
    const float* b1 = (const float*)d_in[8 + s];
    const float* W2 = (const float*)d_in[9 + s];
    const float* b2 = (const float*)d_in[10 + s];
    const float* W3 = (const float*)d_in[11 + s];
    const float* b3 = (const float*)d_in[12 + s];
    const float* W4 = (const float*)d_in[13 + s];
    const float* b4 = (const float*)d_in[14 + s];

    float* out = (float*)d_out;
    float* probs = out + (out_size - 2 * BSZ);
    float* lossp = (out_size > 2 * BSZ) ? out : nullptr;

    float *buf0, *buf1, *xr, *w1r, *w2r, *w3r;
    cudaGetSymbolAddress((void**)&buf0, g_buf0);
    cudaGetSymbolAddress((void**)&buf1, g_buf1);
    cudaGetSymbolAddress((void**)&xr,   g_xr);
    cudaGetSymbolAddress((void**)&w1r,  g_w1r);
    cudaGetSymbolAddress((void**)&w2r,  g_w2r);
    cudaGetSymbolAddress((void**)&w3r,  g_w3r);

    // prep: tf32-round x and weights (elementwise; layouts unchanged)
    {
        int n4;
        n4 = BSZ * FF / 4; round4_kernel<<<(n4 + 255) / 256, 256>>>(x,  xr,  n4);
        n4 = FF  * HH / 4; round4_kernel<<<(n4 + 255) / 256, 256>>>(W1, w1r, n4);
        n4 = HH  * HH / 4; round4_kernel<<<(n4 + 255) / 256, 256>>>(W2, w2r, n4);
        n4 = HH  * HH / 4; round4_kernel<<<(n4 + 255) / 256, 256>>>(W3, w3r, n4);
    }

    // loss (deterministic two-pass)
    loss_partial_kernel<<<DD, 256>>>(dm, alpha, sl, cst);
    if (lossp) loss_final_kernel<<<1, 1024>>>(lossp);

    cudaFuncSetAttribute(gemm_mma, cudaFuncAttributeMaxDynamicSharedMemorySize, SMEM_DYN);

    dim3 grid(HH / BN, BSZ / BM);  // (16, 128)
    gemm_mma<<<grid, 256, SMEM_DYN>>>(xr,   w1r, b1, buf0, FF, HH, FF / BK);
    gemm_mma<<<grid, 256, SMEM_DYN>>>(buf0, w2r, b2, buf1, HH, HH, HH / BK);
    gemm_mma<<<grid, 256, SMEM_DYN>>>(buf1, w3r, b3, buf0, HH, HH, HH / BK);

    layer4_kernel<<<BSZ, 256>>>(buf0, W4, b4, probs);
}

// round 9
// speedup vs baseline: 1.2540x; 1.1743x over previous
#include <cuda_runtime.h>
#include <cstdint>
#include <math.h>

// Problem constants (fixed shapes from reference)
#define BSZ 16384   // batch
#define FF  2048    // n_features
#define HH  4096    // n_hidden
#define DD  4096    // num_of_demos
#define KK  2048    // num_of_features (loss K)

// Scratch (no cudaMalloc allowed)
static __device__ float g_buf0[(size_t)BSZ * HH];
static __device__ float g_buf1[(size_t)BSZ * HH];
static __device__ float g_xr  [(size_t)BSZ * FF];
static __device__ float g_w1r [(size_t)FF  * HH];
static __device__ float g_w2r [(size_t)HH  * HH];
static __device__ float g_w3r [(size_t)HH  * HH];
static __device__ float g_partial[DD];

// ---------------------------------------------------------------------------
// helpers
// ---------------------------------------------------------------------------
__device__ __forceinline__ uint32_t f2tf(float x) {
    uint32_t r;
    asm("cvt.rna.tf32.f32 %0, %1;" : "=r"(r) : "f"(x));
    return r;
}
__device__ __forceinline__ float rna_f(float x) { return __uint_as_float(f2tf(x)); }

__device__ __forceinline__ uint32_t smem_u32(const void* p) {
    uint32_t a;
    asm("{ .reg .u64 t; cvta.to.shared.u64 t, %1; cvt.u32.u64 %0, t; }" : "=r"(a) : "l"(p));
    return a;
}
__device__ __forceinline__ void cp_async16(uint32_t dst, const void* src) {
    asm volatile("cp.async.cg.shared.global [%0], [%1], 16;" :: "r"(dst), "l"(src) : "memory");
}
__device__ __forceinline__ uint32_t lds32(uint32_t addr) {
    uint32_t v;
    asm volatile("ld.shared.b32 %0, [%1];" : "=r"(v) : "r"(addr));
    return v;
}
__device__ __forceinline__ void mma8(float c[4], const uint32_t a[4], const uint32_t b[2]) {
    asm volatile(
        "mma.sync.aligned.m16n8k8.row.col.f32.tf32.tf32.f32 "
        "{%0,%1,%2,%3}, {%4,%5,%6,%7}, {%8,%9}, {%0,%1,%2,%3};\n"
        : "+f"(c[0]), "+f"(c[1]), "+f"(c[2]), "+f"(c[3])
        : "r"(a[0]), "r"(a[1]), "r"(a[2]), "r"(a[3]), "r"(b[0]), "r"(b[1]));
}

__device__ __forceinline__ float block_sum(float v) {
    #pragma unroll
    for (int o = 16; o; o >>= 1) v += __shfl_xor_sync(0xffffffffu, v, o);
    __shared__ float sh[32];
    const int w = threadIdx.x >> 5;
    if ((threadIdx.x & 31) == 0) sh[w] = v;
    __syncthreads();
    const int nw = (blockDim.x + 31) >> 5;
    v = (threadIdx.x < (unsigned)nw) ? sh[threadIdx.x] : 0.f;
    if (threadIdx.x < 32) {
        #pragma unroll
        for (int o = 16; o; o >>= 1) v += __shfl_xor_sync(0xffffffffu, v, o);
    }
    __syncthreads();
    return v;
}

// ---------------------------------------------------------------------------
// prep: fused tf32 rounding of x, W1, W2, W3 (one launch; memory-bound)
// ---------------------------------------------------------------------------
__global__ void round_all_kernel(const float* __restrict__ s0, float* __restrict__ d0, int n0,
                                 const float* __restrict__ s1, float* __restrict__ d1, int n1,
                                 const float* __restrict__ s2, float* __restrict__ d2, int n2,
                                 const float* __restrict__ s3, float* __restrict__ d3, int n3) {
    int i = blockIdx.x * blockDim.x + threadIdx.x;
    const float* s; float* d; int j = i;
    if (j < n0) { s = s0; d = d0; }
    else if ((j -= n0) < n1) { s = s1; d = d1; }
    else if ((j -= n1) < n2) { s = s2; d = d2; }
    else if ((j -= n2) < n3) { s = s3; d = d3; }
    else return;
    float4 v = ((const float4*)s)[j];
    v.x = rna_f(v.x); v.y = rna_f(v.y); v.z = rna_f(v.z); v.w = rna_f(v.w);
    ((float4*)d)[j] = v;
}

// ---------------------------------------------------------------------------
// Loss kernels (unchanged, passing)
// ---------------------------------------------------------------------------
__global__ void loss_partial_kernel(const float* __restrict__ dm,
                                    const float* __restrict__ alpha,
                                    const float* __restrict__ sl,
                                    const float* __restrict__ cptr) {
    const int j = blockIdx.x;
    const size_t base = (size_t)j * KK;
    const float c = cptr[0];
    float s = 0.f;
    for (int k = threadIdx.x; k < KK; k += blockDim.x) {
        float m = fmaf(alpha[k], sl[base + k] - dm[base + k], 1.0f);
        s += fmaxf(m, 0.f) - c;
    }
    float tot = block_sum(s);
    if (threadIdx.x == 0) g_partial[j] = tot;
}
__global__ void loss_final_kernel(float* __restrict__ lossp) {
    float s = 0.f;
    for (int i = threadIdx.x; i < DD; i += blockDim.x) s += g_partial[i];
    float tot = block_sum(s);
    if (threadIdx.x == 0) lossp[0] = tot;
}

// ---------------------------------------------------------------------------
// GEMM: C[M,N] = rna(relu(A[M,K] @ W[K,N] + bias))
// Block 128x128x32, 128 threads (4 warps as 2Mx2N), warp tile 64x64.
// tf32 mma.sync m16n8k8, fp32 accum. 3-stage cp.async pipeline, wait_group 1.
// Sized for 2 CTAs/SM (3 x 33.8KB = 101KB smem/CTA) to cover stall bubbles.
// A smem: 128 rows x 128B, XOR-swizzled 16B chunks (chunk ^= row&7)   [CF]
// B smem: 32 rows x 544B (136 floats; 136 mod 32 = 8)                  [CF]
// Inputs must already hold tf32-rounded bits (prep kernel / epilogue).
// ---------------------------------------------------------------------------
#define BM 128
#define BN 128
#define BK 32
#define BROW 544              // B smem row stride in bytes (136 floats)
#define ASTG 16384            // 128 * 128B
#define BSTG (32 * BROW)      // 17408
#define STG_STRIDE (ASTG + BSTG)
#define NSTAGE 3
#define SMEM_DYN (NSTAGE * STG_STRIDE)

__global__ __launch_bounds__(128, 2)
void gemm_mma(const float* __restrict__ A, const float* __restrict__ W,
              const float* __restrict__ bias, float* __restrict__ C,
              int lda, int N, int ktiles) {
    extern __shared__ char dsm[];
    const uint32_t smb = smem_u32(dsm);

    const int tid = threadIdx.x, lane = tid & 31, wid = tid >> 5;
    const int wm = wid & 1, wn = wid >> 1;      // 2 warps along M, 2 along N
    const int gID = lane >> 2, tig = lane & 3;
    const int bm = blockIdx.y, bn = blockIdx.x;

    const float* Abase = A + (size_t)bm * BM * lda;
    const float* Wbase = W + (size_t)bn * BN;

    // ---- stage fill (cp.async, 16 x 16B per thread) ----
    auto issue_stage = [&](int kt, int s) {
        const float* Ag = Abase + kt * BK;
        const float* Wg = Wbase + (size_t)kt * BK * N;
        const uint32_t sa = smb + s * STG_STRIDE;
        const uint32_t sb = sa + ASTG;
        #pragma unroll
        for (int i = 0; i < 8; ++i) {           // A: 1024 chunks / 128 thr
            const int ci = tid + 128 * i;
            const int r = ci >> 3, cc = ci & 7;
            cp_async16(sa + r * 128 + ((cc ^ (r & 7)) << 4),
                       Ag + (size_t)r * lda + cc * 4);
        }
        #pragma unroll
        for (int i = 0; i < 8; ++i) {           // B: 1024 chunks / 128 thr
            const int ci = tid + 128 * i;
            const int r = ci >> 5, cc = ci & 31;
            cp_async16(sb + r * BROW + (cc << 4),
                       Wg + (size_t)r * N + cc * 4);
        }
        asm volatile("cp.async.commit_group;" ::: "memory");
    };

    issue_stage(0, 0);
    issue_stage(1, 1);

    float acc[4][8][4];
    #pragma unroll
    for (int mt = 0; mt < 4; ++mt)
        #pragma unroll
        for (int nt = 0; nt < 8; ++nt)
            #pragma unroll
            for (int r = 0; r < 4; ++r) acc[mt][nt][r] = 0.f;

    #pragma unroll 1
    for (int kt = 0; kt < ktiles; ++kt) {
        const int s = kt % NSTAGE;
        asm volatile("cp.async.wait_group 1;" ::: "memory");
        __syncthreads();
        if (kt + 2 < ktiles) issue_stage(kt + 2, (kt + 2) % NSTAGE);
        else asm volatile("cp.async.commit_group;" ::: "memory");  // keep invariant

        const uint32_t sa = smb + s * STG_STRIDE;
        const uint32_t sb = sa + ASTG;

        #pragma unroll
        for (int kk = 0; kk < BK; kk += 8) {
            const int cch = kk >> 2;
            uint32_t a[4][4], b[8][2];
            #pragma unroll
            for (int mt = 0; mt < 4; ++mt) {
                const int r0 = wm * 64 + mt * 16 + gID;
                const int r1 = r0 + 8;
                const uint32_t b0 = sa + r0 * 128 + (tig << 2);
                const uint32_t b1 = sa + r1 * 128 + (tig << 2);
                a[mt][0] = lds32(b0 + ((cch       ^ (r0 & 7)) << 4));
                a[mt][1] = lds32(b1 + ((cch       ^ (r1 & 7)) << 4));
                a[mt][2] = lds32(b0 + (((cch + 1) ^ (r0 & 7)) << 4));
                a[mt][3] = lds32(b1 + (((cch + 1) ^ (r1 & 7)) << 4));
            }
            #pragma unroll
            for (int nt = 0; nt < 8; ++nt) {
                const int n = wn * 64 + nt * 8 + gID;
                const uint32_t adr = sb + (kk + tig) * BROW + (n << 2);
                b[nt][0] = lds32(adr);
                b[nt][1] = lds32(adr + 4 * BROW);
            }
            #pragma unroll
            for (int mt = 0; mt < 4; ++mt)
                #pragma unroll
                for (int nt = 0; nt < 8; ++nt)
                    mma8(acc[mt][nt], a[mt], b[nt]);
        }
    }

    // Epilogue: bias + relu + tf32-round, float2 stores
    #pragma unroll
    for (int mt = 0; mt < 4; ++mt) {
        const int m0 = bm * BM + wm * 64 + mt * 16 + gID;
        #pragma unroll
        for (int nt = 0; nt < 8; ++nt) {
            const int n = bn * BN + wn * 64 + nt * 8 + tig * 2;
            const float bx = bias[n], by = bias[n + 1];
            float2 v0, v1;
            v0.x = rna_f(fmaxf(acc[mt][nt][0] + bx, 0.f));
            v0.y = rna_f(fmaxf(acc[mt][nt][1] + by, 0.f));
            v1.x = rna_f(fmaxf(acc[mt][nt][2] + bx, 0.f));
            v1.y = rna_f(fmaxf(acc[mt][nt][3] + by, 0.f));
            *(float2*)&C[(size_t)m0 * N + n]       = v0;
            *(float2*)&C[(size_t)(m0 + 8) * N + n] = v1;
        }
    }
}

// ---------------------------------------------------------------------------
// Final layer: probs = sigmoid(h3 @ W4 + b4) (unchanged, passing)
// ---------------------------------------------------------------------------
__global__ void layer4_kernel(const float* __restrict__ h, const float* __restrict__ w4,
                              const float* __restrict__ b4, float* __restrict__ probs) {
    const int row = blockIdx.x;
    const float* hr = h + (size_t)row * HH;
    float s0 = 0.f, s1 = 0.f;
    for (int k = threadIdx.x; k < HH; k += blockDim.x) {
        const float v = hr[k];
        const float2 w = *(const float2*)(w4 + 2 * k);
        s0 = fmaf(v, w.x, s0);
        s1 = fmaf(v, w.y, s1);
    }
    #pragma unroll
    for (int o = 16; o; o >>= 1) {
        s0 += __shfl_xor_sync(0xffffffffu, s0, o);
        s1 += __shfl_xor_sync(0xffffffffu, s1, o);
    }
    __shared__ float sh0[8], sh1[8];
    const int w = threadIdx.x >> 5;
    if ((threadIdx.x & 31) == 0) { sh0[w] = s0; sh1[w] = s1; }
    __syncthreads();
    if (threadIdx.x == 0) {
        float t0 = 0.f, t1 = 0.f;
        #pragma unroll
        for (int i = 0; i < 8; ++i) { t0 += sh0[i]; t1 += sh1[i]; }
        t0 += b4[0]; t1 += b4[1];
        probs[2 * row]     = 1.f / (1.f + expf(-t0));
        probs[2 * row + 1] = 1.f / (1.f + expf(-t1));
    }
}

// ---------------------------------------------------------------------------
// Launch
// ---------------------------------------------------------------------------
extern "C" void kernel_launch(void* const* d_in, const int* in_sizes, int n_in,
                              void* d_out, int out_size) {
    const int s = (n_in >= 15) ? 0 : -2;
    const float* x     = (const float*)d_in[0];
    const float* dm    = (const float*)d_in[1];
    const float* alpha = (const float*)d_in[2];
    const float* sl    = (const float*)d_in[3];
    const float* cst   = (const float*)d_in[4];
    const float* W1 = (const float*)d_in[7 + s];
    const float* b1 = (const float*)d_in[8 + s];
    const float* W2 = (const float*)d_in[9 + s];
    const float* b2 = (const float*)d_in[10 + s];
    const float* W3 = (const float*)d_in[11 + s];
    const float* b3 = (const float*)d_in[12 + s];
    const float* W4 = (const float*)d_in[13 + s];
    const float* b4 = (const float*)d_in[14 + s];

    float* out = (float*)d_out;
    float* probs = out + (out_size - 2 * BSZ);
    float* lossp = (out_size > 2 * BSZ) ? out : nullptr;

    float *buf0, *buf1, *xr, *w1r, *w2r, *w3r;
    cudaGetSymbolAddress((void**)&buf0, g_buf0);
    cudaGetSymbolAddress((void**)&buf1, g_buf1);
    cudaGetSymbolAddress((void**)&xr,   g_xr);
    cudaGetSymbolAddress((void**)&w1r,  g_w1r);
    cudaGetSymbolAddress((void**)&w2r,  g_w2r);
    cudaGetSymbolAddress((void**)&w3r,  g_w3r);

    // prep: tf32-round x and weights in ONE launch
    {
        const int n0 = BSZ * FF / 4, n1 = FF * HH / 4, n2 = HH * HH / 4, n3 = HH * HH / 4;
        const int tot = n0 + n1 + n2 + n3;
        round_all_kernel<<<(tot + 255) / 256, 256>>>(x, xr, n0, W1, w1r, n1,
                                                     W2, w2r, n2, W3, w3r, n3);
    }

    // loss (deterministic two-pass)
    loss_partial_kernel<<<DD, 256>>>(dm, alpha, sl, cst);
    if (lossp) loss_final_kernel<<<1, 1024>>>(lossp);

    cudaFuncSetAttribute(gemm_mma, cudaFuncAttributeMaxDynamicSharedMemorySize, SMEM_DYN);

    dim3 grid(HH / BN, BSZ / BM);  // (32, 128)
    gemm_mma<<<grid, 128, SMEM_DYN>>>(xr,   w1r, b1, buf0, FF, HH, FF / BK);
    gemm_mma<<<grid, 128, SMEM_DYN>>>(buf0, w2r, b2, buf1, HH, HH, HH / BK);
    gemm_mma<<<grid, 128, SMEM_DYN>>>(buf1, w3r, b3, buf0, HH, HH, HH / BK);

    layer4_kernel<<<BSZ, 256>>>(buf0, W4, b4, probs);
}

// round 10
// speedup vs baseline: 1.3705x; 1.0929x over previous
#include <cuda_runtime.h>
#include <cstdint>
#include <math.h>

// Problem constants (fixed shapes from reference)
#define BSZ 16384   // batch
#define FF  2048    // n_features
#define HH  4096    // n_hidden
#define DD  4096    // num_of_demos
#define KK  2048    // num_of_features (loss K)

// Scratch (no cudaMalloc allowed)
static __device__ float g_buf0[(size_t)BSZ * HH];
static __device__ float g_buf1[(size_t)BSZ * HH];
static __device__ float g_xr  [(size_t)BSZ * FF];
static __device__ float g_w1t [(size_t)FF  * HH];   // [N=HH][K=FF]
static __device__ float g_w2t [(size_t)HH  * HH];   // [N][K]
static __device__ float g_w3t [(size_t)HH  * HH];   // [N][K]
static __device__ float g_partial[DD];

// ---------------------------------------------------------------------------
// helpers
// ---------------------------------------------------------------------------
__device__ __forceinline__ uint32_t f2tf(float x) {
    uint32_t r;
    asm("cvt.rna.tf32.f32 %0, %1;" : "=r"(r) : "f"(x));
    return r;
}
__device__ __forceinline__ float rna_f(float x) { return __uint_as_float(f2tf(x)); }

__device__ __forceinline__ uint32_t smem_u32(const void* p) {
    uint32_t a;
    asm("{ .reg .u64 t; cvta.to.shared.u64 t, %1; cvt.u32.u64 %0, t; }" : "=r"(a) : "l"(p));
    return a;
}
__device__ __forceinline__ void cp_async16(uint32_t dst, const void* src) {
    asm volatile("cp.async.cg.shared.global [%0], [%1], 16;" :: "r"(dst), "l"(src) : "memory");
}
__device__ __forceinline__ void ldsm4(uint32_t r[4], uint32_t addr) {
    asm volatile("ldmatrix.sync.aligned.m8n8.x4.shared.b16 {%0,%1,%2,%3}, [%4];"
                 : "=r"(r[0]), "=r"(r[1]), "=r"(r[2]), "=r"(r[3]) : "r"(addr));
}
__device__ __forceinline__ void mma8(float c[4], const uint32_t a[4], const uint32_t b[2]) {
    asm volatile(
        "mma.sync.aligned.m16n8k8.row.col.f32.tf32.tf32.f32 "
        "{%0,%1,%2,%3}, {%4,%5,%6,%7}, {%8,%9}, {%0,%1,%2,%3};\n"
        : "+f"(c[0]), "+f"(c[1]), "+f"(c[2]), "+f"(c[3])
        : "r"(a[0]), "r"(a[1]), "r"(a[2]), "r"(a[3]), "r"(b[0]), "r"(b[1]));
}

__device__ __forceinline__ float block_sum(float v) {
    #pragma unroll
    for (int o = 16; o; o >>= 1) v += __shfl_xor_sync(0xffffffffu, v, o);
    __shared__ float sh[32];
    const int w = threadIdx.x >> 5;
    if ((threadIdx.x & 31) == 0) sh[w] = v;
    __syncthreads();
    const int nw = (blockDim.x + 31) >> 5;
    v = (threadIdx.x < (unsigned)nw) ? sh[threadIdx.x] : 0.f;
    if (threadIdx.x < 32) {
        #pragma unroll
        for (int o = 16; o; o >>= 1) v += __shfl_xor_sync(0xffffffffu, v, o);
    }
    __syncthreads();
    return v;
}

// ---------------------------------------------------------------------------
// prep: tf32 rounding (x), transpose+round (weights -> [N][K])
// ---------------------------------------------------------------------------
__global__ void round4_kernel(const float* __restrict__ s, float* __restrict__ d, int n4) {
    int i = blockIdx.x * blockDim.x + threadIdx.x;
    if (i < n4) {
        float4 v = ((const float4*)s)[i];
        v.x = rna_f(v.x); v.y = rna_f(v.y); v.z = rna_f(v.z); v.w = rna_f(v.w);
        ((float4*)d)[i] = v;
    }
}

// W[K,N] row-major -> WT[N,K] row-major, rna-rounded
__global__ void transpose_round_kernel(const float* __restrict__ W, float* __restrict__ WT,
                                       int K, int N) {
    __shared__ float t[32][33];
    const int n0 = blockIdx.x * 32, k0 = blockIdx.y * 32;
    const int tx = threadIdx.x, ty = threadIdx.y;
    #pragma unroll
    for (int r = 0; r < 4; ++r)
        t[ty + r * 8][tx] = W[(size_t)(k0 + ty + r * 8) * N + n0 + tx];
    __syncthreads();
    #pragma unroll
    for (int r = 0; r < 4; ++r)
        WT[(size_t)(n0 + ty + r * 8) * K + k0 + tx] = rna_f(t[tx][ty + r * 8]);
}

// ---------------------------------------------------------------------------
// Loss kernels (unchanged, passing)
// ---------------------------------------------------------------------------
__global__ void loss_partial_kernel(const float* __restrict__ dm,
                                    const float* __restrict__ alpha,
                                    const float* __restrict__ sl,
                                    const float* __restrict__ cptr) {
    const int j = blockIdx.x;
    const size_t base = (size_t)j * KK;
    const float c = cptr[0];
    float s = 0.f;
    for (int k = threadIdx.x; k < KK; k += blockDim.x) {
        float m = fmaf(alpha[k], sl[base + k] - dm[base + k], 1.0f);
        s += fmaxf(m, 0.f) - c;
    }
    float tot = block_sum(s);
    if (threadIdx.x == 0) g_partial[j] = tot;
}
__global__ void loss_final_kernel(float* __restrict__ lossp) {
    float s = 0.f;
    for (int i = threadIdx.x; i < DD; i += blockDim.x) s += g_partial[i];
    float tot = block_sum(s);
    if (threadIdx.x == 0) lossp[0] = tot;
}

// ---------------------------------------------------------------------------
// GEMM: C[M,N] = rna(relu(A[M,K] @ Wt^T + bias)),  Wt is [N][K] row-major.
// Block 128x128x32, 128 threads (4 warps as 2Mx2N), warp tile 64x64.
// Both operands: 128 rows x 128B smem tiles, XOR-swizzled 16B chunks
// (chunk ^= row&7) -> conflict-free for cp.async fill AND ldmatrix reads.
// Fragments via ldmatrix.m8n8.x4 (A and B): 8 LDSM + 32 HMMA per kk-step.
// 3-stage cp.async pipeline, wait_group 1, 2 CTAs/SM (96KB smem/CTA).
// Inputs must already hold tf32-rounded bits (prep kernels / epilogue).
// ---------------------------------------------------------------------------
#define BM 128
#define BN 128
#define BK 32
#define ASTG 16384            // 128 rows * 128B
#define BSTG 16384            // 128 rows * 128B
#define STG_STRIDE (ASTG + BSTG)
#define NSTAGE 3
#define SMEM_DYN (NSTAGE * STG_STRIDE)

__global__ __launch_bounds__(128, 2)
void gemm_mma(const float* __restrict__ A, const float* __restrict__ Wt,
              const float* __restrict__ bias, float* __restrict__ C,
              int lda, int ldb, int N, int ktiles) {
    extern __shared__ char dsm[];
    const uint32_t smb = smem_u32(dsm);

    const int tid = threadIdx.x, lane = tid & 31, wid = tid >> 5;
    const int wm = wid & 1, wn = wid >> 1;      // 2 warps along M, 2 along N
    const int gID = lane >> 2, tig = lane & 3;
    const int lj = lane >> 3, li = lane & 7;    // ldmatrix tile index / row
    const int bm = blockIdx.y, bn = blockIdx.x;

    const float* Abase = A  + (size_t)bm * BM * lda;
    const float* Bbase = Wt + (size_t)bn * BN * ldb;

    // ldmatrix per-thread row/chunk decomposition (row&7 == li for both ops)
    const int rowA = wm * 64 + (lj & 1) * 8 + li;      // + mt*16
    const int dchA = lj >> 1;                          // chunk delta for A
    const int rowB = wn * 64 + (lj >> 1) * 8 + li;     // + ntp*16
    const int dchB = lj & 1;                           // chunk delta for B

    // ---- stage fill (cp.async, 16 x 16B per thread) ----
    auto issue_stage = [&](int kt, int s) {
        const float* Ag = Abase + kt * BK;
        const float* Bg = Bbase + kt * BK;
        const uint32_t sa = smb + s * STG_STRIDE;
        const uint32_t sb = sa + ASTG;
        #pragma unroll
        for (int i = 0; i < 8; ++i) {           // A: 1024 chunks / 128 thr
            const int ci = tid + 128 * i;
            const int r = ci >> 3, cc = ci & 7;
            cp_async16(sa + r * 128 + ((cc ^ (r & 7)) << 4),
                       Ag + (size_t)r * lda + cc * 4);
        }
        #pragma unroll
        for (int i = 0; i < 8; ++i) {           // B: 1024 chunks / 128 thr
            const int ci = tid + 128 * i;
            const int r = ci >> 3, cc = ci & 7;
            cp_async16(sb + r * 128 + ((cc ^ (r & 7)) << 4),
                       Bg + (size_t)r * ldb + cc * 4);
        }
        asm volatile("cp.async.commit_group;" ::: "memory");
    };

    issue_stage(0, 0);
    issue_stage(1, 1);

    float acc[4][8][4];
    #pragma unroll
    for (int mt = 0; mt < 4; ++mt)
        #pragma unroll
        for (int nt = 0; nt < 8; ++nt)
            #pragma unroll
            for (int r = 0; r < 4; ++r) acc[mt][nt][r] = 0.f;

    #pragma unroll 1
    for (int kt = 0; kt < ktiles; ++kt) {
        const int s = kt % NSTAGE;
        asm volatile("cp.async.wait_group 1;" ::: "memory");
        __syncthreads();
        if (kt + 2 < ktiles) issue_stage(kt + 2, (kt + 2) % NSTAGE);
        else asm volatile("cp.async.commit_group;" ::: "memory");  // keep invariant

        const uint32_t sa = smb + s * STG_STRIDE;
        const uint32_t sb = sa + ASTG;

        #pragma unroll
        for (int kk = 0; kk < BK; kk += 8) {
            const int cch = kk >> 2;
            uint32_t a[4][4], b[4][4];
            #pragma unroll
            for (int mt = 0; mt < 4; ++mt) {
                const int r = rowA + mt * 16;
                ldsm4(a[mt], sa + r * 128 + (((cch + dchA) ^ li) << 4));
            }
            #pragma unroll
            for (int ntp = 0; ntp < 4; ++ntp) {
                const int r = rowB + ntp * 16;
                ldsm4(b[ntp], sb + r * 128 + (((cch + dchB) ^ li) << 4));
            }
            #pragma unroll
            for (int mt = 0; mt < 4; ++mt)
                #pragma unroll
                for (int ntp = 0; ntp < 4; ++ntp) {
                    mma8(acc[mt][2 * ntp],     a[mt], &b[ntp][0]);
                    mma8(acc[mt][2 * ntp + 1], a[mt], &b[ntp][2]);
                }
        }
    }

    // Epilogue: bias + relu + tf32-round, float2 stores
    #pragma unroll
    for (int mt = 0; mt < 4; ++mt) {
        const int m0 = bm * BM + wm * 64 + mt * 16 + gID;
        #pragma unroll
        for (int nt = 0; nt < 8; ++nt) {
            const int n = bn * BN + wn * 64 + nt * 8 + tig * 2;
            const float bx = bias[n], by = bias[n + 1];
            float2 v0, v1;
            v0.x = rna_f(fmaxf(acc[mt][nt][0] + bx, 0.f));
            v0.y = rna_f(fmaxf(acc[mt][nt][1] + by, 0.f));
            v1.x = rna_f(fmaxf(acc[mt][nt][2] + bx, 0.f));
            v1.y = rna_f(fmaxf(acc[mt][nt][3] + by, 0.f));
            *(float2*)&C[(size_t)m0 * N + n]       = v0;
            *(float2*)&C[(size_t)(m0 + 8) * N + n] = v1;
        }
    }
}

// ---------------------------------------------------------------------------
// Final layer: probs = sigmoid(h3 @ W4 + b4) (unchanged, passing)
// ---------------------------------------------------------------------------
__global__ void layer4_kernel(const float* __restrict__ h, const float* __restrict__ w4,
                              const float* __restrict__ b4, float* __restrict__ probs) {
    const int row = blockIdx.x;
    const float* hr = h + (size_t)row * HH;
    float s0 = 0.f, s1 = 0.f;
    for (int k = threadIdx.x; k < HH; k += blockDim.x) {
        const float v = hr[k];
        const float2 w = *(const float2*)(w4 + 2 * k);
        s0 = fmaf(v, w.x, s0);
        s1 = fmaf(v, w.y, s1);
    }
    #pragma unroll
    for (int o = 16; o; o >>= 1) {
        s0 += __shfl_xor_sync(0xffffffffu, s0, o);
        s1 += __shfl_xor_sync(0xffffffffu, s1, o);
    }
    __shared__ float sh0[8], sh1[8];
    const int w = threadIdx.x >> 5;
    if ((threadIdx.x & 31) == 0) { sh0[w] = s0; sh1[w] = s1; }
    __syncthreads();
    if (threadIdx.x == 0) {
        float t0 = 0.f, t1 = 0.f;
        #pragma unroll
        for (int i = 0; i < 8; ++i) { t0 += sh0[i]; t1 += sh1[i]; }
        t0 += b4[0]; t1 += b4[1];
        probs[2 * row]     = 1.f / (1.f + expf(-t0));
        probs[2 * row + 1] = 1.f / (1.f + expf(-t1));
    }
}

// ---------------------------------------------------------------------------
// Launch
// ---------------------------------------------------------------------------
extern "C" void kernel_launch(void* const* d_in, const int* in_sizes, int n_in,
                              void* d_out, int out_size) {
    const int s = (n_in >= 15) ? 0 : -2;
    const float* x     = (const float*)d_in[0];
    const float* dm    = (const float*)d_in[1];
    const float* alpha = (const float*)d_in[2];
    const float* sl    = (const float*)d_in[3];
    const float* cst   = (const float*)d_in[4];
    const float* W1 = (const float*)d_in[7 + s];
    const float* b1 = (const float*)d_in[8 + s];
    const float* W2 = (const float*)d_in[9 + s];
    const float* b2 = (const float*)d_in[10 + s];
    const float* W3 = (const float*)d_in[11 + s];
    const float* b3 = (const float*)d_in[12 + s];
    const float* W4 = (const float*)d_in[13 + s];
    const float* b4 = (const float*)d_in[14 + s];

    float* out = (float*)d_out;
    float* probs = out + (out_size - 2 * BSZ);
    float* lossp = (out_size > 2 * BSZ) ? out : nullptr;

    float *buf0, *buf1, *xr, *w1t, *w2t, *w3t;
    cudaGetSymbolAddress((void**)&buf0, g_buf0);
    cudaGetSymbolAddress((void**)&buf1, g_buf1);
    cudaGetSymbolAddress((void**)&xr,   g_xr);
    cudaGetSymbolAddress((void**)&w1t,  g_w1t);
    cudaGetSymbolAddress((void**)&w2t,  g_w2t);
    cudaGetSymbolAddress((void**)&w3t,  g_w3t);

    // prep: round x; transpose+round weights to [N][K]
    {
        const int n4 = BSZ * FF / 4;
        round4_kernel<<<(n4 + 255) / 256, 256>>>(x, xr, n4);
        transpose_round_kernel<<<dim3(HH / 32, FF / 32), dim3(32, 8)>>>(W1, w1t, FF, HH);
        transpose_round_kernel<<<dim3(HH / 32, HH / 32), dim3(32, 8)>>>(W2, w2t, HH, HH);
        transpose_round_kernel<<<dim3(HH / 32, HH / 32), dim3(32, 8)>>>(W3, w3t, HH, HH);
    }

    // loss (deterministic two-pass)
    loss_partial_kernel<<<DD, 256>>>(dm, alpha, sl, cst);
    if (lossp) loss_final_kernel<<<1, 1024>>>(lossp);

    cudaFuncSetAttribute(gemm_mma, cudaFuncAttributeMaxDynamicSharedMemorySize, SMEM_DYN);

    dim3 grid(HH / BN, BSZ / BM);  // (32, 128)
    gemm_mma<<<grid, 128, SMEM_DYN>>>(xr,   w1t, b1, buf0, FF, FF, HH, FF / BK);
    gemm_mma<<<grid, 128, SMEM_DYN>>>(buf0, w2t, b2, buf1, HH, HH, HH, HH / BK);
    gemm_mma<<<grid, 128, SMEM_DYN>>>(buf1, w3t, b3, buf0, HH, HH, HH, HH / BK);

    layer4_kernel<<<BSZ, 256>>>(buf0, W4, b4, probs);
}

// round 11
// speedup vs baseline: 2.5517x; 1.8619x over previous
#include <cuda_runtime.h>
#include <cuda_fp16.h>
#include <cstdint>
#include <math.h>

// Problem constants (fixed shapes from reference)
#define BSZ 16384   // batch
#define FF  2048    // n_features
#define HH  4096    // n_hidden
#define DD  4096    // num_of_demos
#define KK  2048    // num_of_features (loss K)

// Scratch (no cudaMalloc allowed). Declared as float arrays; fp16 data is
// stored into them via casts (avoids __half global-init issues).
static __device__ float g_buf0[(size_t)BSZ * HH / 2];   // fp16 activations
static __device__ float g_buf1[(size_t)BSZ * HH / 2];   // fp16 activations
static __device__ float g_xr  [(size_t)BSZ * FF / 2];   // fp16 x
static __device__ float g_w1t [(size_t)FF  * HH / 2];   // fp16 [N=HH][K=FF]
static __device__ float g_w2t [(size_t)HH  * HH / 2];   // fp16 [N][K]
static __device__ float g_w3t [(size_t)HH  * HH / 2];   // fp16 [N][K]
static __device__ float g_partial[DD];

// ---------------------------------------------------------------------------
// helpers
// ---------------------------------------------------------------------------
__device__ __forceinline__ uint32_t smem_u32(const void* p) {
    uint32_t a;
    asm("{ .reg .u64 t; cvta.to.shared.u64 t, %1; cvt.u32.u64 %0, t; }" : "=r"(a) : "l"(p));
    return a;
}
__device__ __forceinline__ void cp_async16(uint32_t dst, const void* src) {
    asm volatile("cp.async.cg.shared.global [%0], [%1], 16;" :: "r"(dst), "l"(src) : "memory");
}
__device__ __forceinline__ void ldsm4(uint32_t r[4], uint32_t addr) {
    asm volatile("ldmatrix.sync.aligned.m8n8.x4.shared.b16 {%0,%1,%2,%3}, [%4];"
                 : "=r"(r[0]), "=r"(r[1]), "=r"(r[2]), "=r"(r[3]) : "r"(addr));
}
// fp16 MMA, fp32 accumulate: D[16x8] += A[16x16] * B[16x8]
__device__ __forceinline__ void mma16(float c[4], const uint32_t a[4], const uint32_t b[2]) {
    asm volatile(
        "mma.sync.aligned.m16n8k16.row.col.f32.f16.f16.f32 "
        "{%0,%1,%2,%3}, {%4,%5,%6,%7}, {%8,%9}, {%0,%1,%2,%3};\n"
        : "+f"(c[0]), "+f"(c[1]), "+f"(c[2]), "+f"(c[3])
        : "r"(a[0]), "r"(a[1]), "r"(a[2]), "r"(a[3]), "r"(b[0]), "r"(b[1]));
}

__device__ __forceinline__ float block_sum(float v) {
    #pragma unroll
    for (int o = 16; o; o >>= 1) v += __shfl_xor_sync(0xffffffffu, v, o);
    __shared__ float sh[32];
    const int w = threadIdx.x >> 5;
    if ((threadIdx.x & 31) == 0) sh[w] = v;
    __syncthreads();
    const int nw = (blockDim.x + 31) >> 5;
    v = (threadIdx.x < (unsigned)nw) ? sh[threadIdx.x] : 0.f;
    if (threadIdx.x < 32) {
        #pragma unroll
        for (int o = 16; o; o >>= 1) v += __shfl_xor_sync(0xffffffffu, v, o);
    }
    __syncthreads();
    return v;
}

// ---------------------------------------------------------------------------
// prep: x -> fp16; weights -> transposed [N][K] fp16
// ---------------------------------------------------------------------------
__global__ void cvt_half_kernel(const float* __restrict__ s, __half* __restrict__ d, int n4) {
    int i = blockIdx.x * blockDim.x + threadIdx.x;
    if (i < n4) {
        float4 v = ((const float4*)s)[i];
        __half2 h0 = __floats2half2_rn(v.x, v.y);
        __half2 h1 = __floats2half2_rn(v.z, v.w);
        ((__half2*)d)[2 * i]     = h0;
        ((__half2*)d)[2 * i + 1] = h1;
    }
}

// W[K,N] row-major f32 -> WT[N,K] row-major fp16
__global__ void transpose_half_kernel(const float* __restrict__ W, __half* __restrict__ WT,
                                      int K, int N) {
    __shared__ float t[32][33];
    const int n0 = blockIdx.x * 32, k0 = blockIdx.y * 32;
    const int tx = threadIdx.x, ty = threadIdx.y;
    #pragma unroll
    for (int r = 0; r < 4; ++r)
        t[ty + r * 8][tx] = W[(size_t)(k0 + ty + r * 8) * N + n0 + tx];
    __syncthreads();
    #pragma unroll
    for (int r = 0; r < 4; ++r)
        WT[(size_t)(n0 + ty + r * 8) * K + k0 + tx] = __float2half_rn(t[tx][ty + r * 8]);
}

// ---------------------------------------------------------------------------
// Loss kernels (unchanged, passing)
// ---------------------------------------------------------------------------
__global__ void loss_partial_kernel(const float* __restrict__ dm,
                                    const float* __restrict__ alpha,
                                    const float* __restrict__ sl,
                                    const float* __restrict__ cptr) {
    const int j = blockIdx.x;
    const size_t base = (size_t)j * KK;
    const float c = cptr[0];
    float s = 0.f;
    for (int k = threadIdx.x; k < KK; k += blockDim.x) {
        float m = fmaf(alpha[k], sl[base + k] - dm[base + k], 1.0f);
        s += fmaxf(m, 0.f) - c;
    }
    float tot = block_sum(s);
    if (threadIdx.x == 0) g_partial[j] = tot;
}
__global__ void loss_final_kernel(float* __restrict__ lossp) {
    float s = 0.f;
    for (int i = threadIdx.x; i < DD; i += blockDim.x) s += g_partial[i];
    float tot = block_sum(s);
    if (threadIdx.x == 0) lossp[0] = tot;
}

// ---------------------------------------------------------------------------
// GEMM (fp16 in, fp32 accum, fp16 out):
//   C[M,N] = fp16(relu(A[M,K] @ Wt^T + bias)),  Wt is [N][K] fp16 row-major.
// Block 128x128x64, 128 threads (4 warps as 2Mx2N), warp tile 64x64.
// mma.sync m16n8k16 f16 (2x tf32 rate). Both smem tiles: 128 rows x 128B
// (BK=64 halves), XOR-swizzled 16B chunks (chunk ^= row&7) -> conflict-free
// for cp.async fill and ldmatrix. 3-stage pipeline, 2 CTAs/SM (96KB each).
// ---------------------------------------------------------------------------
#define BM 128
#define BN 128
#define BK 64                 // K-halves per tile (128B rows)
#define ASTG 16384            // 128 rows * 128B
#define BSTG 16384
#define STG_STRIDE (ASTG + BSTG)
#define NSTAGE 3
#define SMEM_DYN (NSTAGE * STG_STRIDE)

__global__ __launch_bounds__(128, 2)
void gemm_f16(const __half* __restrict__ A, const __half* __restrict__ Wt,
              const float* __restrict__ bias, __half* __restrict__ C,
              int lda, int ldb, int N, int ktiles) {
    extern __shared__ char dsm[];
    const uint32_t smb = smem_u32(dsm);

    const int tid = threadIdx.x, lane = tid & 31, wid = tid >> 5;
    const int wm = wid & 1, wn = wid >> 1;      // 2 warps along M, 2 along N
    const int gID = lane >> 2, tig = lane & 3;
    const int lj = lane >> 3, li = lane & 7;    // ldmatrix tile / row-in-tile
    const int bm = blockIdx.y, bn = blockIdx.x;

    const __half* Abase = A  + (size_t)bm * BM * lda;
    const __half* Bbase = Wt + (size_t)bn * BN * ldb;

    // ldmatrix decomposition (m16n8k16):
    //  A x4 tiles -> a0..a3 = {(r0-7,k0-7),(r8-15,k0-7),(r0-7,k8-15),(r8-15,k8-15)}
    //  B x4 tiles -> {b0,b1} of n-tile, then {b0,b1} of n-tile+8
    const int rowA = wm * 64 + (lj & 1) * 8 + li;      // + mt*16
    const int dchA = lj >> 1;                          // 16B-chunk delta (8 halves)
    const int rowB = wn * 64 + (lj >> 1) * 8 + li;     // + ntp*16
    const int dchB = lj & 1;

    // ---- stage fill (cp.async, 16 x 16B per thread) ----
    auto issue_stage = [&](int kt, int s) {
        const __half* Ag = Abase + (size_t)kt * BK;
        const __half* Bg = Bbase + (size_t)kt * BK;
        const uint32_t sa = smb + s * STG_STRIDE;
        const uint32_t sb = sa + ASTG;
        #pragma unroll
        for (int i = 0; i < 8; ++i) {           // A: 1024 chunks / 128 thr
            const int ci = tid + 128 * i;
            const int r = ci >> 3, cc = ci & 7;
            cp_async16(sa + r * 128 + ((cc ^ (r & 7)) << 4),
                       Ag + (size_t)r * lda + cc * 8);
        }
        #pragma unroll
        for (int i = 0; i < 8; ++i) {           // B: 1024 chunks / 128 thr
            const int ci = tid + 128 * i;
            const int r = ci >> 3, cc = ci & 7;
            cp_async16(sb + r * 128 + ((cc ^ (r & 7)) << 4),
                       Bg + (size_t)r * ldb + cc * 8);
        }
        asm volatile("cp.async.commit_group;" ::: "memory");
    };

    issue_stage(0, 0);
    issue_stage(1, 1);

    float acc[4][8][4];
    #pragma unroll
    for (int mt = 0; mt < 4; ++mt)
        #pragma unroll
        for (int nt = 0; nt < 8; ++nt)
            #pragma unroll
            for (int r = 0; r < 4; ++r) acc[mt][nt][r] = 0.f;

    #pragma unroll 1
    for (int kt = 0; kt < ktiles; ++kt) {
        const int s = kt % NSTAGE;
        asm volatile("cp.async.wait_group 1;" ::: "memory");
        __syncthreads();
        if (kt + 2 < ktiles) issue_stage(kt + 2, (kt + 2) % NSTAGE);
        else asm volatile("cp.async.commit_group;" ::: "memory");  // keep invariant

        const uint32_t sa = smb + s * STG_STRIDE;
        const uint32_t sb = sa + ASTG;

        #pragma unroll
        for (int ks = 0; ks < 4; ++ks) {        // 4 x k16 steps = BK 64
            const int cb = 2 * ks;
            uint32_t a[4][4], b[4][4];
            #pragma unroll
            for (int mt = 0; mt < 4; ++mt) {
                const int r = rowA + mt * 16;
                ldsm4(a[mt], sa + r * 128 + (((cb + dchA) ^ li) << 4));
            }
            #pragma unroll
            for (int ntp = 0; ntp < 4; ++ntp) {
                const int r = rowB + ntp * 16;
                ldsm4(b[ntp], sb + r * 128 + (((cb + dchB) ^ li) << 4));
            }
            #pragma unroll
            for (int mt = 0; mt < 4; ++mt)
                #pragma unroll
                for (int ntp = 0; ntp < 4; ++ntp) {
                    mma16(acc[mt][2 * ntp],     a[mt], &b[ntp][0]);
                    mma16(acc[mt][2 * ntp + 1], a[mt], &b[ntp][2]);
                }
        }
    }

    // Epilogue: bias + relu + fp16 round, half2 stores
    #pragma unroll
    for (int mt = 0; mt < 4; ++mt) {
        const int m0 = bm * BM + wm * 64 + mt * 16 + gID;
        #pragma unroll
        for (int nt = 0; nt < 8; ++nt) {
            const int n = bn * BN + wn * 64 + nt * 8 + tig * 2;
            const float bx = bias[n], by = bias[n + 1];
            __half2 v0 = __floats2half2_rn(fmaxf(acc[mt][nt][0] + bx, 0.f),
                                           fmaxf(acc[mt][nt][1] + by, 0.f));
            __half2 v1 = __floats2half2_rn(fmaxf(acc[mt][nt][2] + bx, 0.f),
                                           fmaxf(acc[mt][nt][3] + by, 0.f));
            *(__half2*)&C[(size_t)m0 * N + n]       = v0;
            *(__half2*)&C[(size_t)(m0 + 8) * N + n] = v1;
        }
    }
}

// ---------------------------------------------------------------------------
// Final layer: probs = sigmoid(h3 @ W4 + b4), h3 fp16, W4 f32 [H,2]
// ---------------------------------------------------------------------------
__global__ void layer4_kernel(const __half* __restrict__ h, const float* __restrict__ w4,
                              const float* __restrict__ b4, float* __restrict__ probs) {
    const int row = blockIdx.x;
    const __half* hr = h + (size_t)row * HH;
    float s0 = 0.f, s1 = 0.f;
    for (int k = threadIdx.x; k < HH / 2; k += blockDim.x) {
        const __half2 h2 = ((const __half2*)hr)[k];
        const float2 f = __half22float2(h2);
        const float4 w = ((const float4*)w4)[k];   // rows 2k, 2k+1
        s0 = fmaf(f.x, w.x, s0); s0 = fmaf(f.y, w.z, s0);
        s1 = fmaf(f.x, w.y, s1); s1 = fmaf(f.y, w.w, s1);
    }
    #pragma unroll
    for (int o = 16; o; o >>= 1) {
        s0 += __shfl_xor_sync(0xffffffffu, s0, o);
        s1 += __shfl_xor_sync(0xffffffffu, s1, o);
    }
    __shared__ float sh0[8], sh1[8];
    const int w = threadIdx.x >> 5;
    if ((threadIdx.x & 31) == 0) { sh0[w] = s0; sh1[w] = s1; }
    __syncthreads();
    if (threadIdx.x == 0) {
        float t0 = 0.f, t1 = 0.f;
        #pragma unroll
        for (int i = 0; i < 8; ++i) { t0 += sh0[i]; t1 += sh1[i]; }
        t0 += b4[0]; t1 += b4[1];
        probs[2 * row]     = 1.f / (1.f + expf(-t0));
        probs[2 * row + 1] = 1.f / (1.f + expf(-t1));
    }
}

// ---------------------------------------------------------------------------
// Launch
// ---------------------------------------------------------------------------
extern "C" void kernel_launch(void* const* d_in, const int* in_sizes, int n_in,
                              void* d_out, int out_size) {
    const int s = (n_in >= 15) ? 0 : -2;
    const float* x     = (const float*)d_in[0];
    const float* dm    = (const float*)d_in[1];
    const float* alpha = (const float*)d_in[2];
    const float* sl    = (const float*)d_in[3];
    const float* cst   = (const float*)d_in[4];
    const float* W1 = (const float*)d_in[7 + s];
    const float* b1 = (const float*)d_in[8 + s];
    const float* W2 = (const float*)d_in[9 + s];
    const float* b2 = (const float*)d_in[10 + s];
    const float* W3 = (const float*)d_in[11 + s];
    const float* b3 = (const float*)d_in[12 + s];
    const float* W4 = (const float*)d_in[13 + s];
    const float* b4 = (const float*)d_in[14 + s];

    float* out = (float*)d_out;
    float* probs = out + (out_size - 2 * BSZ);
    float* lossp = (out_size > 2 * BSZ) ? out : nullptr;

    void *p0, *p1, *pxr, *pw1, *pw2, *pw3;
    cudaGetSymbolAddress(&p0,  g_buf0);
    cudaGetSymbolAddress(&p1,  g_buf1);
    cudaGetSymbolAddress(&pxr, g_xr);
    cudaGetSymbolAddress(&pw1, g_w1t);
    cudaGetSymbolAddress(&pw2, g_w2t);
    cudaGetSymbolAddress(&pw3, g_w3t);
    __half* buf0 = (__half*)p0;
    __half* buf1 = (__half*)p1;
    __half* xr   = (__half*)pxr;
    __half* w1t  = (__half*)pw1;
    __half* w2t  = (__half*)pw2;
    __half* w3t  = (__half*)pw3;

    // prep: x -> fp16; weights -> [N][K] fp16
    {
        const int n4 = BSZ * FF / 4;
        cvt_half_kernel<<<(n4 + 255) / 256, 256>>>(x, xr, n4);
        transpose_half_kernel<<<dim3(HH / 32, FF / 32), dim3(32, 8)>>>(W1, w1t, FF, HH);
        transpose_half_kernel<<<dim3(HH / 32, HH / 32), dim3(32, 8)>>>(W2, w2t, HH, HH);
        transpose_half_kernel<<<dim3(HH / 32, HH / 32), dim3(32, 8)>>>(W3, w3t, HH, HH);
    }

    // loss (deterministic two-pass)
    loss_partial_kernel<<<DD, 256>>>(dm, alpha, sl, cst);
    if (lossp) loss_final_kernel<<<1, 1024>>>(lossp);

    cudaFuncSetAttribute(gemm_f16, cudaFuncAttributeMaxDynamicSharedMemorySize, SMEM_DYN);

    dim3 grid(HH / BN, BSZ / BM);  // (32, 128)
    gemm_f16<<<grid, 128, SMEM_DYN>>>(xr,   w1t, b1, buf0, FF, FF, HH, FF / BK);
    gemm_f16<<<grid, 128, SMEM_DYN>>>(buf0, w2t, b2, buf1, HH, HH, HH, HH / BK);
    gemm_f16<<<grid, 128, SMEM_DYN>>>(buf1, w3t, b3, buf0, HH, HH, HH, HH / BK);

    layer4_kernel<<<BSZ, 256>>>(buf0, W4, b4, probs);
}

// round 12
// speedup vs baseline: 2.5824x; 1.0120x over previous
#include <cuda_runtime.h>
#include <cuda_fp16.h>
#include <cstdint>
#include <math.h>

// Problem constants (fixed shapes from reference)
#define BSZ 16384   // batch
#define FF  2048    // n_features
#define HH  4096    // n_hidden
#define DD  4096    // num_of_demos
#define KK  2048    // num_of_features (loss K)

// Scratch (no cudaMalloc allowed). Declared as float arrays; fp16 data is
// stored into them via casts.
static __device__ float g_buf0[(size_t)BSZ * HH / 2];   // fp16 activations
static __device__ float g_buf1[(size_t)BSZ * HH / 2];   // fp16 activations
static __device__ float g_xr  [(size_t)BSZ * FF / 2];   // fp16 x
static __device__ float g_w1t [(size_t)FF  * HH / 2];   // fp16 [N=HH][K=FF]
static __device__ float g_w2t [(size_t)HH  * HH / 2];   // fp16 [N][K]
static __device__ float g_w3t [(size_t)HH  * HH / 2];   // fp16 [N][K]
static __device__ float g_partial[DD];

// ---------------------------------------------------------------------------
// helpers
// ---------------------------------------------------------------------------
__device__ __forceinline__ uint32_t smem_u32(const void* p) {
    uint32_t a;
    asm("{ .reg .u64 t; cvta.to.shared.u64 t, %1; cvt.u32.u64 %0, t; }" : "=r"(a) : "l"(p));
    return a;
}
__device__ __forceinline__ void cp_async16(uint32_t dst, const void* src) {
    asm volatile("cp.async.cg.shared.global [%0], [%1], 16;" :: "r"(dst), "l"(src) : "memory");
}
__device__ __forceinline__ void ldsm4(uint32_t r[4], uint32_t addr) {
    asm volatile("ldmatrix.sync.aligned.m8n8.x4.shared.b16 {%0,%1,%2,%3}, [%4];"
                 : "=r"(r[0]), "=r"(r[1]), "=r"(r[2]), "=r"(r[3]) : "r"(addr));
}
// fp16 MMA, fp32 accumulate: D[16x8] += A[16x16] * B[16x8]
__device__ __forceinline__ void mma16(float c[4], const uint32_t a[4], const uint32_t b[2]) {
    asm volatile(
        "mma.sync.aligned.m16n8k16.row.col.f32.f16.f16.f32 "
        "{%0,%1,%2,%3}, {%4,%5,%6,%7}, {%8,%9}, {%0,%1,%2,%3};\n"
        : "+f"(c[0]), "+f"(c[1]), "+f"(c[2]), "+f"(c[3])
        : "r"(a[0]), "r"(a[1]), "r"(a[2]), "r"(a[3]), "r"(b[0]), "r"(b[1]));
}

__device__ __forceinline__ float block_sum(float v) {
    #pragma unroll
    for (int o = 16; o; o >>= 1) v += __shfl_xor_sync(0xffffffffu, v, o);
    __shared__ float sh[32];
    const int w = threadIdx.x >> 5;
    if ((threadIdx.x & 31) == 0) sh[w] = v;
    __syncthreads();
    const int nw = (blockDim.x + 31) >> 5;
    v = (threadIdx.x < (unsigned)nw) ? sh[threadIdx.x] : 0.f;
    if (threadIdx.x < 32) {
        #pragma unroll
        for (int o = 16; o; o >>= 1) v += __shfl_xor_sync(0xffffffffu, v, o);
    }
    __syncthreads();
    return v;
}

// ---------------------------------------------------------------------------
// prep: x -> fp16; all 3 weights -> transposed [N][K] fp16 in ONE launch
// ---------------------------------------------------------------------------
__global__ void cvt_half_kernel(const float* __restrict__ s, __half* __restrict__ d, int n4) {
    int i = blockIdx.x * blockDim.x + threadIdx.x;
    if (i < n4) {
        float4 v = ((const float4*)s)[i];
        ((__half2*)d)[2 * i]     = __floats2half2_rn(v.x, v.y);
        ((__half2*)d)[2 * i + 1] = __floats2half2_rn(v.z, v.w);
    }
}

// blockIdx.z selects weight: 0->W1(K=FF), 1->W2, 2->W3 (K=HH). N=HH for all.
__global__ void transpose_all_kernel(const float* __restrict__ W1, __half* __restrict__ T1,
                                     const float* __restrict__ W2, __half* __restrict__ T2,
                                     const float* __restrict__ W3, __half* __restrict__ T3) {
    const int which = blockIdx.z;
    const float* W; __half* WT; int K;
    if (which == 0)      { W = W1; WT = T1; K = FF; }
    else if (which == 1) { W = W2; WT = T2; K = HH; }
    else                 { W = W3; WT = T3; K = HH; }

    const int n0 = blockIdx.x * 32, k0 = blockIdx.y * 32;
    if (k0 >= K) return;

    __shared__ float t[32][33];
    const int tx = threadIdx.x, ty = threadIdx.y;
    #pragma unroll
    for (int r = 0; r < 4; ++r)
        t[ty + r * 8][tx] = W[(size_t)(k0 + ty + r * 8) * HH + n0 + tx];
    __syncthreads();
    #pragma unroll
    for (int r = 0; r < 4; ++r)
        WT[(size_t)(n0 + ty + r * 8) * K + k0 + tx] = __float2half_rn(t[tx][ty + r * 8]);
}

// ---------------------------------------------------------------------------
// Loss kernels (unchanged, passing)
// ---------------------------------------------------------------------------
__global__ void loss_partial_kernel(const float* __restrict__ dm,
                                    const float* __restrict__ alpha,
                                    const float* __restrict__ sl,
                                    const float* __restrict__ cptr) {
    const int j = blockIdx.x;
    const size_t base = (size_t)j * KK;
    const float c = cptr[0];
    float s = 0.f;
    for (int k = threadIdx.x; k < KK; k += blockDim.x) {
        float m = fmaf(alpha[k], sl[base + k] - dm[base + k], 1.0f);
        s += fmaxf(m, 0.f) - c;
    }
    float tot = block_sum(s);
    if (threadIdx.x == 0) g_partial[j] = tot;
}
__global__ void loss_final_kernel(float* __restrict__ lossp) {
    float s = 0.f;
    for (int i = threadIdx.x; i < DD; i += blockDim.x) s += g_partial[i];
    float tot = block_sum(s);
    if (threadIdx.x == 0) lossp[0] = tot;
}

// ---------------------------------------------------------------------------
// GEMM (fp16 in, fp32 accum, fp16 out):
//   C[M,N] = fp16(relu(A[M,K] @ Wt^T + bias)),  Wt is [N][K] fp16 row-major.
// Block 128x128x64, 128 threads (4 warps as 2Mx2N), warp tile 64x64.
// mma.sync m16n8k16 f16. Both smem tiles: 128 rows x 128B, XOR-swizzled
// 16B chunks (chunk ^= row&7) -> conflict-free cp.async + ldmatrix.
// 3-stage cp.async pipeline + REGISTER double-buffered fragments:
// k16-step ks+1's 8 LDSM issue before ks's 32 MMAs (hides LDSM latency).
// 2 CTAs/SM (96KB smem/CTA).
// ---------------------------------------------------------------------------
#define BM 128
#define BN 128
#define BK 64                 // K-halves per tile (128B rows)
#define ASTG 16384            // 128 rows * 128B
#define BSTG 16384
#define STG_STRIDE (ASTG + BSTG)
#define NSTAGE 3
#define SMEM_DYN (NSTAGE * STG_STRIDE)

__global__ __launch_bounds__(128, 2)
void gemm_f16(const __half* __restrict__ A, const __half* __restrict__ Wt,
              const float* __restrict__ bias, __half* __restrict__ C,
              int lda, int ldb, int N, int ktiles) {
    extern __shared__ char dsm[];
    const uint32_t smb = smem_u32(dsm);

    const int tid = threadIdx.x, lane = tid & 31, wid = tid >> 5;
    const int wm = wid & 1, wn = wid >> 1;      // 2 warps along M, 2 along N
    const int gID = lane >> 2, tig = lane & 3;
    const int lj = lane >> 3, li = lane & 7;    // ldmatrix tile / row-in-tile
    const int bm = blockIdx.y, bn = blockIdx.x;

    const __half* Abase = A  + (size_t)bm * BM * lda;
    const __half* Bbase = Wt + (size_t)bn * BN * ldb;

    const int rowA = wm * 64 + (lj & 1) * 8 + li;      // + mt*16
    const int dchA = lj >> 1;
    const int rowB = wn * 64 + (lj >> 1) * 8 + li;     // + ntp*16
    const int dchB = lj & 1;

    // ---- stage fill (cp.async, 16 x 16B per thread) ----
    auto issue_stage = [&](int kt, int s) {
        const __half* Ag = Abase + (size_t)kt * BK;
        const __half* Bg = Bbase + (size_t)kt * BK;
        const uint32_t sa = smb + s * STG_STRIDE;
        const uint32_t sb = sa + ASTG;
        #pragma unroll
        for (int i = 0; i < 8; ++i) {
            const int ci = tid + 128 * i;
            const int r = ci >> 3, cc = ci & 7;
            cp_async16(sa + r * 128 + ((cc ^ (r & 7)) << 4),
                       Ag + (size_t)r * lda + cc * 8);
        }
        #pragma unroll
        for (int i = 0; i < 8; ++i) {
            const int ci = tid + 128 * i;
            const int r = ci >> 3, cc = ci & 7;
            cp_async16(sb + r * 128 + ((cc ^ (r & 7)) << 4),
                       Bg + (size_t)r * ldb + cc * 8);
        }
        asm volatile("cp.async.commit_group;" ::: "memory");
    };

    issue_stage(0, 0);
    issue_stage(1, 1);

    float acc[4][8][4];
    #pragma unroll
    for (int mt = 0; mt < 4; ++mt)
        #pragma unroll
        for (int nt = 0; nt < 8; ++nt)
            #pragma unroll
            for (int r = 0; r < 4; ++r) acc[mt][nt][r] = 0.f;

    uint32_t afr[2][4][4], bfr[2][4][4];   // double-buffered fragments

    #pragma unroll 1
    for (int kt = 0; kt < ktiles; ++kt) {
        const int s = kt % NSTAGE;
        asm volatile("cp.async.wait_group 1;" ::: "memory");
        __syncthreads();
        if (kt + 2 < ktiles) issue_stage(kt + 2, (kt + 2) % NSTAGE);
        else asm volatile("cp.async.commit_group;" ::: "memory");  // keep invariant

        const uint32_t sa = smb + s * STG_STRIDE;
        const uint32_t sb = sa + ASTG;

        // prologue: fragments for ks = 0
        #pragma unroll
        for (int mt = 0; mt < 4; ++mt)
            ldsm4(afr[0][mt], sa + (rowA + mt * 16) * 128 + ((dchA ^ li) << 4));
        #pragma unroll
        for (int ntp = 0; ntp < 4; ++ntp)
            ldsm4(bfr[0][ntp], sb + (rowB + ntp * 16) * 128 + ((dchB ^ li) << 4));

        #pragma unroll
        for (int ks = 0; ks < 4; ++ks) {
            const int cur = ks & 1, nxt = cur ^ 1;
            if (ks < 3) {                       // prefetch ks+1 fragments
                const int cb = 2 * (ks + 1);
                #pragma unroll
                for (int mt = 0; mt < 4; ++mt)
                    ldsm4(afr[nxt][mt],
                          sa + (rowA + mt * 16) * 128 + (((cb + dchA) ^ li) << 4));
                #pragma unroll
                for (int ntp = 0; ntp < 4; ++ntp)
                    ldsm4(bfr[nxt][ntp],
                          sb + (rowB + ntp * 16) * 128 + (((cb + dchB) ^ li) << 4));
            }
            #pragma unroll
            for (int mt = 0; mt < 4; ++mt)
                #pragma unroll
                for (int ntp = 0; ntp < 4; ++ntp) {
                    mma16(acc[mt][2 * ntp],     afr[cur][mt], &bfr[cur][ntp][0]);
                    mma16(acc[mt][2 * ntp + 1], afr[cur][mt], &bfr[cur][ntp][2]);
                }
        }
    }

    // Epilogue: bias + relu + fp16 round, half2 stores
    #pragma unroll
    for (int mt = 0; mt < 4; ++mt) {
        const int m0 = bm * BM + wm * 64 + mt * 16 + gID;
        #pragma unroll
        for (int nt = 0; nt < 8; ++nt) {
            const int n = bn * BN + wn * 64 + nt * 8 + tig * 2;
            const float bx = bias[n], by = bias[n + 1];
            __half2 v0 = __floats2half2_rn(fmaxf(acc[mt][nt][0] + bx, 0.f),
                                           fmaxf(acc[mt][nt][1] + by, 0.f));
            __half2 v1 = __floats2half2_rn(fmaxf(acc[mt][nt][2] + bx, 0.f),
                                           fmaxf(acc[mt][nt][3] + by, 0.f));
            *(__half2*)&C[(size_t)m0 * N + n]       = v0;
            *(__half2*)&C[(size_t)(m0 + 8) * N + n] = v1;
        }
    }
}

// ---------------------------------------------------------------------------
// Final layer: probs = sigmoid(h3 @ W4 + b4), h3 fp16, W4 f32 [H,2]
// ---------------------------------------------------------------------------
__global__ void layer4_kernel(const __half* __restrict__ h, const float* __restrict__ w4,
                              const float* __restrict__ b4, float* __restrict__ probs) {
    const int row = blockIdx.x;
    const __half* hr = h + (size_t)row * HH;
    float s0 = 0.f, s1 = 0.f;
    for (int k = threadIdx.x; k < HH / 2; k += blockDim.x) {
        const __half2 h2 = ((const __half2*)hr)[k];
        const float2 f = __half22float2(h2);
        const float4 w = ((const float4*)w4)[k];   // rows 2k, 2k+1
        s0 = fmaf(f.x, w.x, s0); s0 = fmaf(f.y, w.z, s0);
        s1 = fmaf(f.x, w.y, s1); s1 = fmaf(f.y, w.w, s1);
    }
    #pragma unroll
    for (int o = 16; o; o >>= 1) {
        s0 += __shfl_xor_sync(0xffffffffu, s0, o);
        s1 += __shfl_xor_sync(0xffffffffu, s1, o);
    }
    __shared__ float sh0[8], sh1[8];
    const int w = threadIdx.x >> 5;
    if ((threadIdx.x & 31) == 0) { sh0[w] = s0; sh1[w] = s1; }
    __syncthreads();
    if (threadIdx.x == 0) {
        float t0 = 0.f, t1 = 0.f;
        #pragma unroll
        for (int i = 0; i < 8; ++i) { t0 += sh0[i]; t1 += sh1[i]; }
        t0 += b4[0]; t1 += b4[1];
        probs[2 * row]     = 1.f / (1.f + expf(-t0));
        probs[2 * row + 1] = 1.f / (1.f + expf(-t1));
    }
}

// ---------------------------------------------------------------------------
// Launch
// ---------------------------------------------------------------------------
extern "C" void kernel_launch(void* const* d_in, const int* in_sizes, int n_in,
                              void* d_out, int out_size) {
    const int s = (n_in >= 15) ? 0 : -2;
    const float* x     = (const float*)d_in[0];
    const float* dm    = (const float*)d_in[1];
    const float* alpha = (const float*)d_in[2];
    const float* sl    = (const float*)d_in[3];
    const float* cst   = (const float*)d_in[4];
    const float* W1 = (const float*)d_in[7 + s];
    const float* b1 = (const float*)d_in[8 + s];
    const float* W2 = (const float*)d_in[9 + s];
    const float* b2 = (const float*)d_in[10 + s];
    const float* W3 = (const float*)d_in[11 + s];
    const float* b3 = (const float*)d_in[12 + s];
    const float* W4 = (const float*)d_in[13 + s];
    const float* b4 = (const float*)d_in[14 + s];

    float* out = (float*)d_out;
    float* probs = out + (out_size - 2 * BSZ);
    float* lossp = (out_size > 2 * BSZ) ? out : nullptr;

    void *p0, *p1, *pxr, *pw1, *pw2, *pw3;
    cudaGetSymbolAddress(&p0,  g_buf0);
    cudaGetSymbolAddress(&p1,  g_buf1);
    cudaGetSymbolAddress(&pxr, g_xr);
    cudaGetSymbolAddress(&pw1, g_w1t);
    cudaGetSymbolAddress(&pw2, g_w2t);
    cudaGetSymbolAddress(&pw3, g_w3t);
    __half* buf0 = (__half*)p0;
    __half* buf1 = (__half*)p1;
    __half* xr   = (__half*)pxr;
    __half* w1t  = (__half*)pw1;
    __half* w2t  = (__half*)pw2;
    __half* w3t  = (__half*)pw3;

    // prep: x -> fp16; all weights -> [N][K] fp16 in one launch
    {
        const int n4 = BSZ * FF / 4;
        cvt_half_kernel<<<(n4 + 255) / 256, 256>>>(x, xr, n4);
        transpose_all_kernel<<<dim3(HH / 32, HH / 32, 3), dim3(32, 8)>>>(
            W1, w1t, W2, w2t, W3, w3t);
    }

    // loss (deterministic two-pass)
    loss_partial_kernel<<<DD, 256>>>(dm, alpha, sl, cst);
    if (lossp) loss_final_kernel<<<1, 1024>>>(lossp);

    cudaFuncSetAttribute(gemm_f16, cudaFuncAttributeMaxDynamicSharedMemorySize, SMEM_DYN);

    dim3 grid(HH / BN, BSZ / BM);  // (32, 128)
    gemm_f16<<<grid, 128, SMEM_DYN>>>(xr,   w1t, b1, buf0, FF, FF, HH, FF / BK);
    gemm_f16<<<grid, 128, SMEM_DYN>>>(buf0, w2t, b2, buf1, HH, HH, HH, HH / BK);
    gemm_f16<<<grid, 128, SMEM_DYN>>>(buf1, w3t, b3, buf0, HH, HH, HH, HH / BK);

    layer4_kernel<<<BSZ, 256>>>(buf0, W4, b4, probs);
}

// round 13
// speedup vs baseline: 2.9560x; 1.1447x over previous
#include <cuda_runtime.h>
#include <cuda_fp16.h>
#include <cstdint>
#include <math.h>

// Problem constants (fixed shapes from reference)
#define BSZ 16384   // batch
#define FF  2048    // n_features
#define HH  4096    // n_hidden
#define DD  4096    // num_of_demos
#define KK  2048    // num_of_features (loss K)

// Scratch (no cudaMalloc allowed). Declared as float arrays; fp16 data is
// stored into them via casts.
static __device__ float g_buf0[(size_t)BSZ * HH / 2];   // fp16 activations
static __device__ float g_buf1[(size_t)BSZ * HH / 2];   // fp16 activations
static __device__ float g_xr  [(size_t)BSZ * FF / 2];   // fp16 x
static __device__ float g_w1t [(size_t)FF  * HH / 2];   // fp16 [N=HH][K=FF]
static __device__ float g_w2t [(size_t)HH  * HH / 2];   // fp16 [N][K]
static __device__ float g_w3t [(size_t)HH  * HH / 2];   // fp16 [N][K]
static __device__ float g_partial[DD];

// ---------------------------------------------------------------------------
// helpers
// ---------------------------------------------------------------------------
__device__ __forceinline__ uint32_t smem_u32(const void* p) {
    uint32_t a;
    asm("{ .reg .u64 t; cvta.to.shared.u64 t, %1; cvt.u32.u64 %0, t; }" : "=r"(a) : "l"(p));
    return a;
}
__device__ __forceinline__ void cp_async16(uint32_t dst, const void* src) {
    asm volatile("cp.async.cg.shared.global [%0], [%1], 16;" :: "r"(dst), "l"(src) : "memory");
}
__device__ __forceinline__ void ldsm4(uint32_t r[4], uint32_t addr) {
    asm volatile("ldmatrix.sync.aligned.m8n8.x4.shared.b16 {%0,%1,%2,%3}, [%4];"
                 : "=r"(r[0]), "=r"(r[1]), "=r"(r[2]), "=r"(r[3]) : "r"(addr));
}
// fp16 MMA, fp32 accumulate: D[16x8] += A[16x16] * B[16x8]
__device__ __forceinline__ void mma16(float c[4], const uint32_t a[4], const uint32_t b[2]) {
    asm volatile(
        "mma.sync.aligned.m16n8k16.row.col.f32.f16.f16.f32 "
        "{%0,%1,%2,%3}, {%4,%5,%6,%7}, {%8,%9}, {%0,%1,%2,%3};\n"
        : "+f"(c[0]), "+f"(c[1]), "+f"(c[2]), "+f"(c[3])
        : "r"(a[0]), "r"(a[1]), "r"(a[2]), "r"(a[3]), "r"(b[0]), "r"(b[1]));
}

__device__ __forceinline__ float block_sum(float v) {
    #pragma unroll
    for (int o = 16; o; o >>= 1) v += __shfl_xor_sync(0xffffffffu, v, o);
    __shared__ float sh[32];
    const int w = threadIdx.x >> 5;
    if ((threadIdx.x & 31) == 0) sh[w] = v;
    __syncthreads();
    const int nw = (blockDim.x + 31) >> 5;
    v = (threadIdx.x < (unsigned)nw) ? sh[threadIdx.x] : 0.f;
    if (threadIdx.x < 32) {
        #pragma unroll
        for (int o = 16; o; o >>= 1) v += __shfl_xor_sync(0xffffffffu, v, o);
    }
    __syncthreads();
    return v;
}

// ---------------------------------------------------------------------------
// prep: x -> fp16; all 3 weights -> transposed [N][K] fp16 in ONE launch
// ---------------------------------------------------------------------------
__global__ void cvt_half_kernel(const float* __restrict__ s, __half* __restrict__ d, int n4) {
    int i = blockIdx.x * blockDim.x + threadIdx.x;
    if (i < n4) {
        float4 v = ((const float4*)s)[i];
        ((__half2*)d)[2 * i]     = __floats2half2_rn(v.x, v.y);
        ((__half2*)d)[2 * i + 1] = __floats2half2_rn(v.z, v.w);
    }
}

// blockIdx.z selects weight: 0->W1(K=FF), 1->W2, 2->W3 (K=HH). N=HH for all.
__global__ void transpose_all_kernel(const float* __restrict__ W1, __half* __restrict__ T1,
                                     const float* __restrict__ W2, __half* __restrict__ T2,
                                     const float* __restrict__ W3, __half* __restrict__ T3) {
    const int which = blockIdx.z;
    const float* W; __half* WT; int K;
    if (which == 0)      { W = W1; WT = T1; K = FF; }
    else if (which == 1) { W = W2; WT = T2; K = HH; }
    else                 { W = W3; WT = T3; K = HH; }

    const int n0 = blockIdx.x * 32, k0 = blockIdx.y * 32;
    if (k0 >= K) return;

    __shared__ float t[32][33];
    const int tx = threadIdx.x, ty = threadIdx.y;
    #pragma unroll
    for (int r = 0; r < 4; ++r)
        t[ty + r * 8][tx] = W[(size_t)(k0 + ty + r * 8) * HH + n0 + tx];
    __syncthreads();
    #pragma unroll
    for (int r = 0; r < 4; ++r)
        WT[(size_t)(n0 + ty + r * 8) * K + k0 + tx] = __float2half_rn(t[tx][ty + r * 8]);
}

// ---------------------------------------------------------------------------
// Loss kernels (unchanged, passing)
// ---------------------------------------------------------------------------
__global__ void loss_partial_kernel(const float* __restrict__ dm,
                                    const float* __restrict__ alpha,
                                    const float* __restrict__ sl,
                                    const float* __restrict__ cptr) {
    const int j = blockIdx.x;
    const size_t base = (size_t)j * KK;
    const float c = cptr[0];
    float s = 0.f;
    for (int k = threadIdx.x; k < KK; k += blockDim.x) {
        float m = fmaf(alpha[k], sl[base + k] - dm[base + k], 1.0f);
        s += fmaxf(m, 0.f) - c;
    }
    float tot = block_sum(s);
    if (threadIdx.x == 0) g_partial[j] = tot;
}
__global__ void loss_final_kernel(float* __restrict__ lossp) {
    float s = 0.f;
    for (int i = threadIdx.x; i < DD; i += blockDim.x) s += g_partial[i];
    float tot = block_sum(s);
    if (threadIdx.x == 0) lossp[0] = tot;
}

// ---------------------------------------------------------------------------
// GEMM (fp16 in, fp32 accum, fp16 out):
//   C[M,N] = fp16(relu(A[M,K] @ Wt^T + bias)),  Wt is [N][K] fp16 row-major.
// Block 128x128x64, 128 threads (4 warps as 2Mx2N), warp tile 64x64.
// mma.sync m16n8k16 f16. Both smem tiles: 128 rows x 128B, XOR-swizzled
// 16B chunks (chunk ^= row&7) -> conflict-free cp.async + ldmatrix.
// 3-stage cp.async pipeline + CROSS-TILE register double-buffered fragments:
// invariant "stages kt and kt+1 barrier-visible at tile kt start" lets ks==3
// prefetch tile kt+1's ks0 fragments, so post-barrier MMAs start with zero
// LDSM exposure. Boundary protocol: sync -> issue(kt+3) -> wait_group 1 ->
// sync (first frees refill slot; wait completes group kt+2 per-thread;
// second publishes it). 2 CTAs/SM (96KB smem/CTA).
// ---------------------------------------------------------------------------
#define BM 128
#define BN 128
#define BK 64                 // K-halves per tile (128B rows)
#define ASTG 16384            // 128 rows * 128B
#define BSTG 16384
#define STG_STRIDE (ASTG + BSTG)
#define NSTAGE 3
#define SMEM_DYN (NSTAGE * STG_STRIDE)

__global__ __launch_bounds__(128, 2)
void gemm_f16(const __half* __restrict__ A, const __half* __restrict__ Wt,
              const float* __restrict__ bias, __half* __restrict__ C,
              int lda, int ldb, int N, int ktiles) {
    extern __shared__ char dsm[];
    const uint32_t smb = smem_u32(dsm);

    const int tid = threadIdx.x, lane = tid & 31, wid = tid >> 5;
    const int wm = wid & 1, wn = wid >> 1;      // 2 warps along M, 2 along N
    const int gID = lane >> 2, tig = lane & 3;
    const int lj = lane >> 3, li = lane & 7;    // ldmatrix tile / row-in-tile
    const int bm = blockIdx.y, bn = blockIdx.x;

    const __half* Abase = A  + (size_t)bm * BM * lda;
    const __half* Bbase = Wt + (size_t)bn * BN * ldb;

    const int rowA = wm * 64 + (lj & 1) * 8 + li;      // + mt*16
    const int dchA = lj >> 1;
    const int rowB = wn * 64 + (lj >> 1) * 8 + li;     // + ntp*16
    const int dchB = lj & 1;

    // ---- stage fill (cp.async, 16 x 16B per thread) ----
    auto issue_stage = [&](int kt, int s) {
        const __half* Ag = Abase + (size_t)kt * BK;
        const __half* Bg = Bbase + (size_t)kt * BK;
        const uint32_t sa = smb + s * STG_STRIDE;
        const uint32_t sb = sa + ASTG;
        #pragma unroll
        for (int i = 0; i < 8; ++i) {
            const int ci = tid + 128 * i;
            const int r = ci >> 3, cc = ci & 7;
            cp_async16(sa + r * 128 + ((cc ^ (r & 7)) << 4),
                       Ag + (size_t)r * lda + cc * 8);
        }
        #pragma unroll
        for (int i = 0; i < 8; ++i) {
            const int ci = tid + 128 * i;
            const int r = ci >> 3, cc = ci & 7;
            cp_async16(sb + r * 128 + ((cc ^ (r & 7)) << 4),
                       Bg + (size_t)r * ldb + cc * 8);
        }
        asm volatile("cp.async.commit_group;" ::: "memory");
    };

    // prologue: 3 stages in flight; make stages 0 AND 1 barrier-visible
    issue_stage(0, 0);
    issue_stage(1, 1);
    issue_stage(2, 2);
    asm volatile("cp.async.wait_group 2;" ::: "memory");   // g0 done (per-thread)
    __syncthreads();                                       // stage 0 visible
    asm volatile("cp.async.wait_group 1;" ::: "memory");   // g1 done (per-thread)
    __syncthreads();                                       // stage 1 visible

    float acc[4][8][4];
    #pragma unroll
    for (int mt = 0; mt < 4; ++mt)
        #pragma unroll
        for (int nt = 0; nt < 8; ++nt)
            #pragma unroll
            for (int r = 0; r < 4; ++r) acc[mt][nt][r] = 0.f;

    uint32_t afr[2][4][4], bfr[2][4][4];   // double-buffered fragments

    // fragments for tile 0, ks 0
    {
        const uint32_t sa = smb, sb = smb + ASTG;
        #pragma unroll
        for (int mt = 0; mt < 4; ++mt)
            ldsm4(afr[0][mt], sa + (rowA + mt * 16) * 128 + ((dchA ^ li) << 4));
        #pragma unroll
        for (int ntp = 0; ntp < 4; ++ntp)
            ldsm4(bfr[0][ntp], sb + (rowB + ntp * 16) * 128 + ((dchB ^ li) << 4));
    }

    #pragma unroll 1
    for (int kt = 0; kt < ktiles; ++kt) {
        const uint32_t sa = smb + (kt % NSTAGE) * STG_STRIDE;
        const uint32_t sb = sa + ASTG;
        const uint32_t na = smb + ((kt + 1) % NSTAGE) * STG_STRIDE;  // next tile
        const uint32_t nb = na + ASTG;

        #pragma unroll
        for (int ks = 0; ks < 4; ++ks) {
            const int cur = ks & 1, nxt = cur ^ 1;
            if (ks < 3) {                       // prefetch ks+1 (same stage)
                const int cb = 2 * (ks + 1);
                #pragma unroll
                for (int mt = 0; mt < 4; ++mt)
                    ldsm4(afr[nxt][mt],
                          sa + (rowA + mt * 16) * 128 + (((cb + dchA) ^ li) << 4));
                #pragma unroll
                for (int ntp = 0; ntp < 4; ++ntp)
                    ldsm4(bfr[nxt][ntp],
                          sb + (rowB + ntp * 16) * 128 + (((cb + dchB) ^ li) << 4));
            } else if (kt + 1 < ktiles) {       // prefetch tile kt+1, ks 0
                #pragma unroll
                for (int mt = 0; mt < 4; ++mt)
                    ldsm4(afr[nxt][mt],
                          na + (rowA + mt * 16) * 128 + ((dchA ^ li) << 4));
                #pragma unroll
                for (int ntp = 0; ntp < 4; ++ntp)
                    ldsm4(bfr[nxt][ntp],
                          nb + (rowB + ntp * 16) * 128 + ((dchB ^ li) << 4));
            }
            #pragma unroll
            for (int mt = 0; mt < 4; ++mt)
                #pragma unroll
                for (int ntp = 0; ntp < 4; ++ntp) {
                    mma16(acc[mt][2 * ntp],     afr[cur][mt], &bfr[cur][ntp][0]);
                    mma16(acc[mt][2 * ntp + 1], afr[cur][mt], &bfr[cur][ntp][2]);
                }
        }

        // boundary: free slot kt%3, refill it with tile kt+3, publish stage kt+2
        if (kt + 1 < ktiles) {
            __syncthreads();                    // all warps done reading stage kt
            if (kt + 3 < ktiles) issue_stage(kt + 3, kt % NSTAGE);
            else asm volatile("cp.async.commit_group;" ::: "memory");
            asm volatile("cp.async.wait_group 1;" ::: "memory");  // g(kt+2) done
            __syncthreads();                    // stage kt+2 visible
        }
    }

    // Epilogue: bias + relu + fp16 round, half2 stores
    #pragma unroll
    for (int mt = 0; mt < 4; ++mt) {
        const int m0 = bm * BM + wm * 64 + mt * 16 + gID;
        #pragma unroll
        for (int nt = 0; nt < 8; ++nt) {
            const int n = bn * BN + wn * 64 + nt * 8 + tig * 2;
            const float bx = bias[n], by = bias[n + 1];
            __half2 v0 = __floats2half2_rn(fmaxf(acc[mt][nt][0] + bx, 0.f),
                                           fmaxf(acc[mt][nt][1] + by, 0.f));
            __half2 v1 = __floats2half2_rn(fmaxf(acc[mt][nt][2] + bx, 0.f),
                                           fmaxf(acc[mt][nt][3] + by, 0.f));
            *(__half2*)&C[(size_t)m0 * N + n]       = v0;
            *(__half2*)&C[(size_t)(m0 + 8) * N + n] = v1;
        }
    }
}

// ---------------------------------------------------------------------------
// Final layer: probs = sigmoid(h3 @ W4 + b4), h3 fp16, W4 f32 [H,2]
// ---------------------------------------------------------------------------
__global__ void layer4_kernel(const __half* __restrict__ h, const float* __restrict__ w4,
                              const float* __restrict__ b4, float* __restrict__ probs) {
    const int row = blockIdx.x;
    const __half* hr = h + (size_t)row * HH;
    float s0 = 0.f, s1 = 0.f;
    for (int k = threadIdx.x; k < HH / 2; k += blockDim.x) {
        const __half2 h2 = ((const __half2*)hr)[k];
        const float2 f = __half22float2(h2);
        const float4 w = ((const float4*)w4)[k];   // rows 2k, 2k+1
        s0 = fmaf(f.x, w.x, s0); s0 = fmaf(f.y, w.z, s0);
        s1 = fmaf(f.x, w.y, s1); s1 = fmaf(f.y, w.w, s1);
    }
    #pragma unroll
    for (int o = 16; o; o >>= 1) {
        s0 += __shfl_xor_sync(0xffffffffu, s0, o);
        s1 += __shfl_xor_sync(0xffffffffu, s1, o);
    }
    __shared__ float sh0[8], sh1[8];
    const int w = threadIdx.x >> 5;
    if ((threadIdx.x & 31) == 0) { sh0[w] = s0; sh1[w] = s1; }
    __syncthreads();
    if (threadIdx.x == 0) {
        float t0 = 0.f, t1 = 0.f;
        #pragma unroll
        for (int i = 0; i < 8; ++i) { t0 += sh0[i]; t1 += sh1[i]; }
        t0 += b4[0]; t1 += b4[1];
        probs[2 * row]     = 1.f / (1.f + expf(-t0));
        probs[2 * row + 1] = 1.f / (1.f + expf(-t1));
    }
}

// ---------------------------------------------------------------------------
// Launch
// ---------------------------------------------------------------------------
extern "C" void kernel_launch(void* const* d_in, const int* in_sizes, int n_in,
                              void* d_out, int out_size) {
    const int s = (n_in >= 15) ? 0 : -2;
    const float* x     = (const float*)d_in[0];
    const float* dm    = (const float*)d_in[1];
    const float* alpha = (const float*)d_in[2];
    const float* sl    = (const float*)d_in[3];
    const float* cst   = (const float*)d_in[4];
    const float* W1 = (const float*)d_in[7 + s];
    const float* b1 = (const float*)d_in[8 + s];
    const float* W2 = (const float*)d_in[9 + s];
    const float* b2 = (const float*)d_in[10 + s];
    const float* W3 = (const float*)d_in[11 + s];
    const float* b3 = (const float*)d_in[12 + s];
    const float* W4 = (const float*)d_in[13 + s];
    const float* b4 = (const float*)d_in[14 + s];

    float* out = (float*)d_out;
    float* probs = out + (out_size - 2 * BSZ);
    float* lossp = (out_size > 2 * BSZ) ? out : nullptr;

    void *p0, *p1, *pxr, *pw1, *pw2, *pw3;
    cudaGetSymbolAddress(&p0,  g_buf0);
    cudaGetSymbolAddress(&p1,  g_buf1);
    cudaGetSymbolAddress(&pxr, g_xr);
    cudaGetSymbolAddress(&pw1, g_w1t);
    cudaGetSymbolAddress(&pw2, g_w2t);
    cudaGetSymbolAddress(&pw3, g_w3t);
    __half* buf0 = (__half*)p0;
    __half* buf1 = (__half*)p1;
    __half* xr   = (__half*)pxr;
    __half* w1t  = (__half*)pw1;
    __half* w2t  = (__half*)pw2;
    __half* w3t  = (__half*)pw3;

    // prep: x -> fp16; all weights -> [N][K] fp16 in one launch
    {
        const int n4 = BSZ * FF / 4;
        cvt_half_kernel<<<(n4 + 255) / 256, 256>>>(x, xr, n4);
        transpose_all_kernel<<<dim3(HH / 32, HH / 32, 3), dim3(32, 8)>>>(
            W1, w1t, W2, w2t, W3, w3t);
    }

    // loss (deterministic two-pass)
    loss_partial_kernel<<<DD, 256>>>(dm, alpha, sl, cst);
    if (lossp) loss_final_kernel<<<1, 1024>>>(lossp);

    cudaFuncSetAttribute(gemm_f16, cudaFuncAttributeMaxDynamicSharedMemorySize, SMEM_DYN);

    dim3 grid(HH / BN, BSZ / BM);  // (32, 128)
    gemm_f16<<<grid, 128, SMEM_DYN>>>(xr,   w1t, b1, buf0, FF, FF, HH, FF / BK);
    gemm_f16<<<grid, 128, SMEM_DYN>>>(buf0, w2t, b2, buf1, HH, HH, HH, HH / BK);
    gemm_f16<<<grid, 128, SMEM_DYN>>>(buf1, w3t, b3, buf0, HH, HH, HH, HH / BK);

    layer4_kernel<<<BSZ, 256>>>(buf0, W4, b4, probs);
}

// round 14
// speedup vs baseline: 3.0231x; 1.0227x over previous
#include <cuda_runtime.h>
#include <cuda_fp16.h>
#include <cstdint>
#include <math.h>

// Problem constants (fixed shapes from reference)
#define BSZ 16384   // batch
#define FF  2048    // n_features
#define HH  4096    // n_hidden
#define DD  4096    // num_of_demos
#define KK  2048    // num_of_features (loss K)

// Scratch (no cudaMalloc allowed). fp16 data stored via casts.
static __device__ float g_buf0[(size_t)BSZ * HH / 2];   // fp16 activations
static __device__ float g_buf1[(size_t)BSZ * HH / 2];   // fp16 activations
static __device__ float g_xr  [(size_t)BSZ * FF / 2];   // fp16 x
static __device__ float g_w1t [(size_t)FF  * HH / 2];   // fp16 [N=HH][K=FF]
static __device__ float g_w2t [(size_t)HH  * HH / 2];   // fp16 [N][K]
static __device__ float g_w3t [(size_t)HH  * HH / 2];   // fp16 [N][K]
static __device__ float g_logits[(size_t)BSZ * 2];      // fused layer4 accum
static __device__ float g_partial[DD];

// ---------------------------------------------------------------------------
// helpers
// ---------------------------------------------------------------------------
__device__ __forceinline__ uint32_t smem_u32(const void* p) {
    uint32_t a;
    asm("{ .reg .u64 t; cvta.to.shared.u64 t, %1; cvt.u32.u64 %0, t; }" : "=r"(a) : "l"(p));
    return a;
}
__device__ __forceinline__ void cp_async16(uint32_t dst, const void* src) {
    asm volatile("cp.async.cg.shared.global [%0], [%1], 16;" :: "r"(dst), "l"(src) : "memory");
}
__device__ __forceinline__ void ldsm4(uint32_t r[4], uint32_t addr) {
    asm volatile("ldmatrix.sync.aligned.m8n8.x4.shared.b16 {%0,%1,%2,%3}, [%4];"
                 : "=r"(r[0]), "=r"(r[1]), "=r"(r[2]), "=r"(r[3]) : "r"(addr));
}
__device__ __forceinline__ void mma16(float c[4], const uint32_t a[4], const uint32_t b[2]) {
    asm volatile(
        "mma.sync.aligned.m16n8k16.row.col.f32.f16.f16.f32 "
        "{%0,%1,%2,%3}, {%4,%5,%6,%7}, {%8,%9}, {%0,%1,%2,%3};\n"
        : "+f"(c[0]), "+f"(c[1]), "+f"(c[2]), "+f"(c[3])
        : "r"(a[0]), "r"(a[1]), "r"(a[2]), "r"(a[3]), "r"(b[0]), "r"(b[1]));
}

__device__ __forceinline__ float block_sum(float v) {
    #pragma unroll
    for (int o = 16; o; o >>= 1) v += __shfl_xor_sync(0xffffffffu, v, o);
    __shared__ float sh[32];
    const int w = threadIdx.x >> 5;
    if ((threadIdx.x & 31) == 0) sh[w] = v;
    __syncthreads();
    const int nw = (blockDim.x + 31) >> 5;
    v = (threadIdx.x < (unsigned)nw) ? sh[threadIdx.x] : 0.f;
    if (threadIdx.x < 32) {
        #pragma unroll
        for (int o = 16; o; o >>= 1) v += __shfl_xor_sync(0xffffffffu, v, o);
    }
    __syncthreads();
    return v;
}

// ---------------------------------------------------------------------------
// prep (ONE launch): z=0..2 -> transpose W1..W3 to [N][K] fp16; z=3 -> x fp16
// ---------------------------------------------------------------------------
__global__ void prep_all_kernel(const float* __restrict__ x,  __half* __restrict__ xr,
                                const float* __restrict__ W1, __half* __restrict__ T1,
                                const float* __restrict__ W2, __half* __restrict__ T2,
                                const float* __restrict__ W3, __half* __restrict__ T3) {
    const int z = blockIdx.z;
    const int tx = threadIdx.x, ty = threadIdx.y;
    if (z == 3) {                      // x conversion: 16384 blocks * 512 float4
        const int blk = blockIdx.y * gridDim.x + blockIdx.x;
        const int tid = ty * 32 + tx;
        #pragma unroll
        for (int h = 0; h < 2; ++h) {
            const int i = blk * 512 + h * 256 + tid;   // < BSZ*FF/4 exactly
            float4 v = ((const float4*)x)[i];
            ((__half2*)xr)[2 * i]     = __floats2half2_rn(v.x, v.y);
            ((__half2*)xr)[2 * i + 1] = __floats2half2_rn(v.z, v.w);
        }
        return;
    }
    const float* W; __half* WT; int K;
    if (z == 0)      { W = W1; WT = T1; K = FF; }
    else if (z == 1) { W = W2; WT = T2; K = HH; }
    else             { W = W3; WT = T3; K = HH; }
    const int n0 = blockIdx.x * 32, k0 = blockIdx.y * 32;
    if (k0 >= K) return;
    __shared__ float t[32][33];
    #pragma unroll
    for (int r = 0; r < 4; ++r)
        t[ty + r * 8][tx] = W[(size_t)(k0 + ty + r * 8) * HH + n0 + tx];
    __syncthreads();
    #pragma unroll
    for (int r = 0; r < 4; ++r)
        WT[(size_t)(n0 + ty + r * 8) * K + k0 + tx] = __float2half_rn(t[tx][ty + r * 8]);
}

// ---------------------------------------------------------------------------
// Loss kernels (unchanged, passing)
// ---------------------------------------------------------------------------
__global__ void loss_partial_kernel(const float* __restrict__ dm,
                                    const float* __restrict__ alpha,
                                    const float* __restrict__ sl,
                                    const float* __restrict__ cptr) {
    const int j = blockIdx.x;
    const size_t base = (size_t)j * KK;
    const float c = cptr[0];
    float s = 0.f;
    for (int k = threadIdx.x; k < KK; k += blockDim.x) {
        float m = fmaf(alpha[k], sl[base + k] - dm[base + k], 1.0f);
        s += fmaxf(m, 0.f) - c;
    }
    float tot = block_sum(s);
    if (threadIdx.x == 0) g_partial[j] = tot;
}
__global__ void loss_final_kernel(float* __restrict__ lossp) {
    float s = 0.f;
    for (int i = threadIdx.x; i < DD; i += blockDim.x) s += g_partial[i];
    float tot = block_sum(s);
    if (threadIdx.x == 0) lossp[0] = tot;
}

// ---------------------------------------------------------------------------
// GEMM core (fp16 in, fp32 accum): proven R13 mainloop.
// Block 128x128x64, 4 warps (2Mx2N), warp tile 64x64, m16n8k16.
// 3-stage cp.async + cross-tile register double-buffered ldmatrix fragments.
// FUSE_L4=0: epilogue writes fp16 relu(acc+bias) to C.
// FUSE_L4=1: epilogue dots relu(acc+bias) with W4 and atomically accumulates
//            per-row logits (h3 never materialized).
// ---------------------------------------------------------------------------
#define BM 128
#define BN 128
#define BK 64
#define ASTG 16384
#define BSTG 16384
#define STG_STRIDE (ASTG + BSTG)
#define NSTAGE 3
#define SMEM_DYN (NSTAGE * STG_STRIDE)

template <int FUSE_L4>
__global__ __launch_bounds__(128, 2)
void gemm_f16(const __half* __restrict__ A, const __half* __restrict__ Wt,
              const float* __restrict__ bias, __half* __restrict__ C,
              const float* __restrict__ w4, float* __restrict__ logits,
              int lda, int ldb, int N, int ktiles) {
    extern __shared__ char dsm[];
    const uint32_t smb = smem_u32(dsm);

    const int tid = threadIdx.x, lane = tid & 31, wid = tid >> 5;
    const int wm = wid & 1, wn = wid >> 1;
    const int gID = lane >> 2, tig = lane & 3;
    const int lj = lane >> 3, li = lane & 7;
    const int bm = blockIdx.y, bn = blockIdx.x;

    const __half* Abase = A  + (size_t)bm * BM * lda;
    const __half* Bbase = Wt + (size_t)bn * BN * ldb;

    const int rowA = wm * 64 + (lj & 1) * 8 + li;
    const int dchA = lj >> 1;
    const int rowB = wn * 64 + (lj >> 1) * 8 + li;
    const int dchB = lj & 1;

    auto issue_stage = [&](int kt, int s) {
        const __half* Ag = Abase + (size_t)kt * BK;
        const __half* Bg = Bbase + (size_t)kt * BK;
        const uint32_t sa = smb + s * STG_STRIDE;
        const uint32_t sb = sa + ASTG;
        #pragma unroll
        for (int i = 0; i < 8; ++i) {
            const int ci = tid + 128 * i;
            const int r = ci >> 3, cc = ci & 7;
            cp_async16(sa + r * 128 + ((cc ^ (r & 7)) << 4),
                       Ag + (size_t)r * lda + cc * 8);
        }
        #pragma unroll
        for (int i = 0; i < 8; ++i) {
            const int ci = tid + 128 * i;
            const int r = ci >> 3, cc = ci & 7;
            cp_async16(sb + r * 128 + ((cc ^ (r & 7)) << 4),
                       Bg + (size_t)r * ldb + cc * 8);
        }
        asm volatile("cp.async.commit_group;" ::: "memory");
    };

    issue_stage(0, 0);
    issue_stage(1, 1);
    issue_stage(2, 2);
    asm volatile("cp.async.wait_group 2;" ::: "memory");
    __syncthreads();
    asm volatile("cp.async.wait_group 1;" ::: "memory");
    __syncthreads();

    float acc[4][8][4];
    #pragma unroll
    for (int mt = 0; mt < 4; ++mt)
        #pragma unroll
        for (int nt = 0; nt < 8; ++nt)
            #pragma unroll
            for (int r = 0; r < 4; ++r) acc[mt][nt][r] = 0.f;

    uint32_t afr[2][4][4], bfr[2][4][4];
    {
        const uint32_t sa = smb, sb = smb + ASTG;
        #pragma unroll
        for (int mt = 0; mt < 4; ++mt)
            ldsm4(afr[0][mt], sa + (rowA + mt * 16) * 128 + ((dchA ^ li) << 4));
        #pragma unroll
        for (int ntp = 0; ntp < 4; ++ntp)
            ldsm4(bfr[0][ntp], sb + (rowB + ntp * 16) * 128 + ((dchB ^ li) << 4));
    }

    #pragma unroll 1
    for (int kt = 0; kt < ktiles; ++kt) {
        const uint32_t sa = smb + (kt % NSTAGE) * STG_STRIDE;
        const uint32_t sb = sa + ASTG;
        const uint32_t na = smb + ((kt + 1) % NSTAGE) * STG_STRIDE;
        const uint32_t nb = na + ASTG;

        #pragma unroll
        for (int ks = 0; ks < 4; ++ks) {
            const int cur = ks & 1, nxt = cur ^ 1;
            if (ks < 3) {
                const int cb = 2 * (ks + 1);
                #pragma unroll
                for (int mt = 0; mt < 4; ++mt)
                    ldsm4(afr[nxt][mt],
                          sa + (rowA + mt * 16) * 128 + (((cb + dchA) ^ li) << 4));
                #pragma unroll
                for (int ntp = 0; ntp < 4; ++ntp)
                    ldsm4(bfr[nxt][ntp],
                          sb + (rowB + ntp * 16) * 128 + (((cb + dchB) ^ li) << 4));
            } else if (kt + 1 < ktiles) {
                #pragma unroll
                for (int mt = 0; mt < 4; ++mt)
                    ldsm4(afr[nxt][mt],
                          na + (rowA + mt * 16) * 128 + ((dchA ^ li) << 4));
                #pragma unroll
                for (int ntp = 0; ntp < 4; ++ntp)
                    ldsm4(bfr[nxt][ntp],
                          nb + (rowB + ntp * 16) * 128 + ((dchB ^ li) << 4));
            }
            #pragma unroll
            for (int mt = 0; mt < 4; ++mt)
                #pragma unroll
                for (int ntp = 0; ntp < 4; ++ntp) {
                    mma16(acc[mt][2 * ntp],     afr[cur][mt], &bfr[cur][ntp][0]);
                    mma16(acc[mt][2 * ntp + 1], afr[cur][mt], &bfr[cur][ntp][2]);
                }
        }

        if (kt + 1 < ktiles) {
            __syncthreads();
            if (kt + 3 < ktiles) issue_stage(kt + 3, kt % NSTAGE);
            else asm volatile("cp.async.commit_group;" ::: "memory");
            asm volatile("cp.async.wait_group 1;" ::: "memory");
            __syncthreads();
        }
    }

    if (FUSE_L4 == 0) {
        // bias + relu + fp16 round, half2 stores
        #pragma unroll
        for (int mt = 0; mt < 4; ++mt) {
            const int m0 = bm * BM + wm * 64 + mt * 16 + gID;
            #pragma unroll
            for (int nt = 0; nt < 8; ++nt) {
                const int n = bn * BN + wn * 64 + nt * 8 + tig * 2;
                const float bx = bias[n], by = bias[n + 1];
                __half2 v0 = __floats2half2_rn(fmaxf(acc[mt][nt][0] + bx, 0.f),
                                               fmaxf(acc[mt][nt][1] + by, 0.f));
                __half2 v1 = __floats2half2_rn(fmaxf(acc[mt][nt][2] + bx, 0.f),
                                               fmaxf(acc[mt][nt][3] + by, 0.f));
                *(__half2*)&C[(size_t)m0 * N + n]       = v0;
                *(__half2*)&C[(size_t)(m0 + 8) * N + n] = v1;
            }
        }
    } else {
        // fused layer4: logits[m][c] += sum_n relu(acc+bias)[m][n] * W4[n][c]
        __shared__ float lsm[BM][2];
        if (tid < 64) { lsm[2 * tid][0] = 0.f; lsm[2 * tid][1] = 0.f;
                        lsm[2 * tid + 1][0] = 0.f; lsm[2 * tid + 1][1] = 0.f; }
        __syncthreads();
        #pragma unroll
        for (int mt = 0; mt < 4; ++mt) {
            const int r0 = wm * 64 + mt * 16 + gID;      // local row; r1 = r0+8
            float p00 = 0.f, p01 = 0.f, p10 = 0.f, p11 = 0.f;
            #pragma unroll
            for (int nt = 0; nt < 8; ++nt) {
                const int n = bn * BN + wn * 64 + nt * 8 + tig * 2;
                const float bx = bias[n], by = bias[n + 1];
                const float4 w = *(const float4*)(w4 + 2 * n);  // W4[n], W4[n+1]
                const float h00 = fmaxf(acc[mt][nt][0] + bx, 0.f);
                const float h01 = fmaxf(acc[mt][nt][1] + by, 0.f);
                const float h10 = fmaxf(acc[mt][nt][2] + bx, 0.f);
                const float h11 = fmaxf(acc[mt][nt][3] + by, 0.f);
                p00 = fmaf(h00, w.x, p00); p00 = fmaf(h01, w.z, p00);
                p01 = fmaf(h00, w.y, p01); p01 = fmaf(h01, w.w, p01);
                p10 = fmaf(h10, w.x, p10); p10 = fmaf(h11, w.z, p10);
                p11 = fmaf(h10, w.y, p11); p11 = fmaf(h11, w.w, p11);
            }
            #pragma unroll
            for (int o = 1; o < 4; o <<= 1) {            // reduce over tig
                p00 += __shfl_xor_sync(0xffffffffu, p00, o);
                p01 += __shfl_xor_sync(0xffffffffu, p01, o);
                p10 += __shfl_xor_sync(0xffffffffu, p10, o);
                p11 += __shfl_xor_sync(0xffffffffu, p11, o);
            }
            if (tig == 0) {
                atomicAdd(&lsm[r0][0], p00);
                atomicAdd(&lsm[r0][1], p01);
                atomicAdd(&lsm[r0 + 8][0], p10);
                atomicAdd(&lsm[r0 + 8][1], p11);
            }
        }
        __syncthreads();
        if (tid < BM) {
            const int m = bm * BM + tid;
            atomicAdd(&logits[2 * m],     lsm[tid][0]);
            atomicAdd(&logits[2 * m + 1], lsm[tid][1]);
        }
    }
}

// ---------------------------------------------------------------------------
// sigmoid over fused logits: probs = sigmoid(logits + b4)
// ---------------------------------------------------------------------------
__global__ void sigmoid_kernel(const float* __restrict__ logits,
                               const float* __restrict__ b4,
                               float* __restrict__ probs) {
    const int i = blockIdx.x * blockDim.x + threadIdx.x;   // over BSZ rows
    if (i < BSZ) {
        const float t0 = logits[2 * i]     + b4[0];
        const float t1 = logits[2 * i + 1] + b4[1];
        probs[2 * i]     = 1.f / (1.f + expf(-t0));
        probs[2 * i + 1] = 1.f / (1.f + expf(-t1));
    }
}

// ---------------------------------------------------------------------------
// Launch
// ---------------------------------------------------------------------------
extern "C" void kernel_launch(void* const* d_in, const int* in_sizes, int n_in,
                              void* d_out, int out_size) {
    const int s = (n_in >= 15) ? 0 : -2;
    const float* x     = (const float*)d_in[0];
    const float* dm    = (const float*)d_in[1];
    const float* alpha = (const float*)d_in[2];
    const float* sl    = (const float*)d_in[3];
    const float* cst   = (const float*)d_in[4];
    const float* W1 = (const float*)d_in[7 + s];
    const float* b1 = (const float*)d_in[8 + s];
    const float* W2 = (const float*)d_in[9 + s];
    const float* b2 = (const float*)d_in[10 + s];
    const float* W3 = (const float*)d_in[11 + s];
    const float* b3 = (const float*)d_in[12 + s];
    const float* W4 = (const float*)d_in[13 + s];
    const float* b4 = (const float*)d_in[14 + s];

    float* out = (float*)d_out;
    float* probs = out + (out_size - 2 * BSZ);
    float* lossp = (out_size > 2 * BSZ) ? out : nullptr;

    void *p0, *p1, *pxr, *pw1, *pw2, *pw3, *plg;
    cudaGetSymbolAddress(&p0,  g_buf0);
    cudaGetSymbolAddress(&p1,  g_buf1);
    cudaGetSymbolAddress(&pxr, g_xr);
    cudaGetSymbolAddress(&pw1, g_w1t);
    cudaGetSymbolAddress(&pw2, g_w2t);
    cudaGetSymbolAddress(&pw3, g_w3t);
    cudaGetSymbolAddress(&plg, g_logits);
    __half* buf0 = (__half*)p0;
    __half* buf1 = (__half*)p1;
    __half* xr   = (__half*)pxr;
    __half* w1t  = (__half*)pw1;
    __half* w2t  = (__half*)pw2;
    __half* w3t  = (__half*)pw3;
    float* logits = (float*)plg;

    // prep (one launch): weights -> [N][K] fp16, x -> fp16
    prep_all_kernel<<<dim3(HH / 32, HH / 32, 4), dim3(32, 8)>>>(
        x, xr, W1, w1t, W2, w2t, W3, w3t);

    // loss (deterministic two-pass)
    loss_partial_kernel<<<DD, 256>>>(dm, alpha, sl, cst);
    if (lossp) loss_final_kernel<<<1, 1024>>>(lossp);

    // zero fused-layer4 accumulator (graph-capturable async memset)
    cudaMemsetAsync(logits, 0, (size_t)BSZ * 2 * sizeof(float));

    cudaFuncSetAttribute(gemm_f16<0>, cudaFuncAttributeMaxDynamicSharedMemorySize, SMEM_DYN);
    cudaFuncSetAttribute(gemm_f16<1>, cudaFuncAttributeMaxDynamicSharedMemorySize, SMEM_DYN);

    dim3 grid(HH / BN, BSZ / BM);  // (32, 128)
    gemm_f16<0><<<grid, 128, SMEM_DYN>>>(xr,   w1t, b1, buf0, nullptr, nullptr,
                                         FF, FF, HH, FF / BK);
    gemm_f16<0><<<grid, 128, SMEM_DYN>>>(buf0, w2t, b2, buf1, nullptr, nullptr,
                                         HH, HH, HH, HH / BK);
    gemm_f16<1><<<grid, 128, SMEM_DYN>>>(buf1, w3t, b3, nullptr, W4, logits,
                                         HH, HH, HH, HH / BK);

    sigmoid_kernel<<<(BSZ + 255) / 256, 256>>>(logits, b4, probs);
}